// round 6
// baseline (speedup 1.0000x reference)
#include <cuda_runtime.h>
#include <math.h>
#include <float.h>

#define BB 32
#define AA 8400
#define GG 40
#define CC 80
#define ROW 85
#define SP 1536      // max candidates per batch (row stride); true bound ~1080
#define MM 512       // max matched anchors per batch

// ---------------- scratch (device globals; no allocation) ----------------
__device__ unsigned long long d_match[BB * AA];
__device__ unsigned long long d_cinin[BB * SP];   // per-candidate in-region mask
__device__ int    d_fgidx[BB * SP];
__device__ int    d_inv  [BB * AA];
__device__ int    d_fgcnt[BB];
__device__ int    d_mcnt [BB];
__device__ int    d_midx [BB * MM];
__device__ float  d_cost[(size_t)BB * GG * SP];
__device__ float  d_iou [(size_t)BB * GG * SP];
__device__ double d_acc[6];

// ---------------- kernel 1: fused mask + ordered compaction + init ----------
// One block per batch, 1024 threads = 32 warps, warp w covers anchors
// [w*263, w*263+263). Computes the 40-bit in-region mask analytically,
// zeroes d_match, and compacts candidates in ascending anchor order.
__global__ void __launch_bounds__(1024) k_scan(const float* __restrict__ labels) {
    __shared__ float sgx[GG], sgy[GG];
    __shared__ int wcnt[32];
    int b = blockIdx.x;
    int tid = threadIdx.x, wid = tid >> 5, lane = tid & 31;
    if (tid < GG) {
        sgx[tid] = labels[(b * GG + tid) * 5 + 1];
        sgy[tid] = labels[(b * GG + tid) * 5 + 2];
    }
    if (tid == 0) d_mcnt[b] = 0;
    if (b == 0 && tid < 6) d_acc[tid] = 0.0;
    __syncthreads();

    const int CH = 263;
    int base = wid * CH;
    unsigned long long mymask[9];
    int cnt = 0;
#pragma unroll
    for (int k = 0; k < 9; k++) {
        int loc = k * 32 + lane;
        int a = base + loc;
        unsigned long long m = 0ull;
        if (loc < CH && a < AA) {
            float s; int n, rel;
            if (a < 6400)      { s = 8.0f;  n = 80; rel = a;        }
            else if (a < 8000) { s = 16.0f; n = 40; rel = a - 6400; }
            else               { s = 32.0f; n = 20; rel = a - 8000; }
            float xc = ((float)(rel % n) + 0.5f) * s;
            float yc = ((float)(rel / n) + 0.5f) * s;
            float r  = 1.5f * s;
#pragma unroll 8
            for (int g = 0; g < GG; g++) {
                // equivalent to min(dl,dr,dt,db) > 0 in f32
                bool in = (xc > sgx[g] - r) && (xc < sgx[g] + r) &&
                          (yc > sgy[g] - r) && (yc < sgy[g] + r);
                if (in) m |= (1ull << g);
            }
            d_match[b * AA + a] = 0ull;
        }
        mymask[k] = m;
        cnt += __popc(__ballot_sync(0xffffffffu, m != 0ull));
    }
    if (lane == 0) wcnt[wid] = cnt;
    __syncthreads();
    if (wid == 0) {               // inclusive scan of 32 warp counts
        int v = wcnt[lane];
#pragma unroll
        for (int o = 1; o < 32; o <<= 1) {
            int u = __shfl_up_sync(0xffffffffu, v, o);
            if (lane >= o) v += u;
        }
        wcnt[lane] = v;
    }
    __syncthreads();
    if (tid == 0) {
        int tot = wcnt[31];
        d_fgcnt[b] = tot < SP ? tot : SP;
    }
    int pos = wcnt[wid] - cnt;    // exclusive warp offset
#pragma unroll
    for (int k = 0; k < 9; k++) {
        unsigned long long m = mymask[k];
        unsigned bal = __ballot_sync(0xffffffffu, m != 0ull);
        int my = __popc(bal & ((1u << lane) - 1u));
        if (m != 0ull && pos + my < SP) {
            int a = base + k * 32 + lane;
            int idx = b * SP + pos + my;
            d_fgidx[idx] = a;
            d_cinin[idx] = m;
            d_inv[b * AA + a] = pos + my;
        }
        pos += __popc(bal);
    }
}

// ---------------- kernel 2: fused suml + pairwise cost/iou ----------------
// Block = 128 threads handles 16 candidates. Phase 1: 8 lanes per candidate
// compute suml and stash box/cls/obj in smem. Phase 2: the same 128 threads
// sweep all 640 (cand, g) pairs with coalesced d_cost/d_iou writes.
__global__ void __launch_bounds__(128) k_cost2(const float* __restrict__ outp,
                                               const float* __restrict__ labels) {
    __shared__ float qx1[GG], qx2[GG], qy1[GG], qy2[GG], qar[GG];
    __shared__ int   sgc[GG];
    __shared__ float scls[16][81];
    __shared__ float sx1[16], sy1[16], sx2[16], sy2[16], sar[16], sobj[16], ssum[16];
    __shared__ unsigned long long sinin[16];
    int b = blockIdx.y;
    int cnt = d_fgcnt[b];
    int i0 = blockIdx.x * 16;
    if (i0 >= cnt) return;                        // uniform block exit
    int tid = threadIdx.x;
    if (tid < GG) {
        const float* L = labels + (b * GG + tid) * 5;
        float gxv = L[1], gyv = L[2], gwv = L[3], ghv = L[4];
        sgc[tid] = (int)L[0];
        qx1[tid] = gxv - gwv * 0.5f; qx2[tid] = gxv + gwv * 0.5f;
        qy1[tid] = gyv - ghv * 0.5f; qy2[tid] = gyv + ghv * 0.5f;
        qar[tid] = gwv * ghv;
    }
    // phase 1
    int lane = tid & 31, warp = tid >> 5;
    int grp = lane >> 3, sub = lane & 7;
    int ci = warp * 4 + grp;                      // 0..15
    int i = i0 + ci;
    bool valid = (i < cnt);
    int ic = valid ? i : (cnt - 1);
    int a = d_fgidx[b * SP + ic];
    const float* o = outp + (size_t)(b * AA + a) * ROW;
    float obj = o[4];
    float prod = 1.0f;
#pragma unroll
    for (int c = 0; c < 10; c++) {
        float cv = o[5 + sub * 10 + c];
        scls[ci][sub * 10 + c] = cv;
        float x = cv * obj;
        prod *= (1.0f - x * rsqrtf(x));
    }
    float l = __logf(prod);
    l += __shfl_xor_sync(0xffffffffu, l, 1);
    l += __shfl_xor_sync(0xffffffffu, l, 2);
    l += __shfl_xor_sync(0xffffffffu, l, 4);
    if (sub == 0) {
        float bx = o[0], by = o[1], bw = o[2], bh = o[3];
        sx1[ci] = bx - bw * 0.5f; sy1[ci] = by - bh * 0.5f;
        sx2[ci] = bx + bw * 0.5f; sy2[ci] = by + bh * 0.5f;
        sar[ci] = bw * bh;
        sobj[ci] = obj;
        ssum[ci] = l;
        sinin[ci] = valid ? d_cinin[b * SP + i] : 0ull;
    }
    __syncthreads();
    // phase 2: 640 pairs, g-major for coalesced stores
#pragma unroll
    for (int p = 0; p < 5; p++) {
        int pair = p * 128 + tid;
        int g = pair >> 4;
        int c = pair & 15;
        int i2 = i0 + c;
        if (i2 >= cnt) continue;
        float w = fminf(sx2[c], qx2[g]) - fmaxf(sx1[c], qx1[g]);
        float h = fminf(sy2[c], qy2[g]) - fmaxf(sy1[c], qy1[g]);
        float inter = fmaxf(w, 0.0f) * fmaxf(h, 0.0f);
        float den = sar[c] + qar[g] - inter;
        float y = __uint_as_float(0x7EF311C3u - __float_as_uint(den));
        y = y * (2.0f - den * y);
        y = y * (2.0f - den * y);
        float iou = inter * y;
        size_t off = (size_t)(b * GG + g) * SP + i2;
        d_iou[off] = iou;
        float cost = FLT_MAX;
        if ((sinin[c] >> g) & 1ull) {
            float xg = scls[c][sgc[g]] * sobj[c];
            float pg = xg * rsqrtf(xg);
            cost = -ssum[c] - (0.5f * __logf(xg) - __logf(1.0f - pg))
                   - 3.0f * __logf(iou + 1e-8f);
        }
        d_cost[off] = cost;
    }
}

// ---------------- kernel 3: block-per-(b,g) dynamic_k + stable top-k --------
__global__ void __launch_bounds__(256) k_select() {
    __shared__ unsigned long long swp[8];
    __shared__ unsigned long long sbest;
    int bg = blockIdx.x;
    int b  = bg / GG;
    int tid = threadIdx.x, lane = tid & 31, wid = tid >> 5;
    int N = d_fgcnt[b];
    const float* irow = d_iou  + (size_t)bg * SP;
    const float* crow = d_cost + (size_t)bg * SP;

    unsigned kiou[6], kcst[6];
#pragma unroll
    for (int j = 0; j < 6; j++) {
        int i = tid + j * 256;
        bool v = (i < N);
        kiou[j] = v ? __float_as_uint(irow[i]) : 0u;
        unsigned cb = v ? __float_as_uint(crow[i]) : 0x7F800000u;
        kcst[j] = (cb & 0x80000000u) ? ~cb : (cb | 0x80000000u);
    }

    // phase A: sum of top-10 iou values
    float sum = 0.0f;
    unsigned long long prev = ~0ull;
    for (int t = 0; t < 10; t++) {
        unsigned long long best = 0ull;
#pragma unroll
        for (int j = 0; j < 6; j++) {
            unsigned long long key =
                ((unsigned long long)kiou[j] << 32) | (unsigned)(tid + j * 256);
            if (key < prev && key > best) best = key;
        }
#pragma unroll
        for (int o = 16; o > 0; o >>= 1) {
            unsigned long long oth = __shfl_xor_sync(0xffffffffu, best, o);
            if (oth > best) best = oth;
        }
        if (lane == 0) swp[wid] = best;
        __syncthreads();
        if (tid == 0) {
            unsigned long long m = swp[0];
#pragma unroll
            for (int w2 = 1; w2 < 8; w2++) if (swp[w2] > m) m = swp[w2];
            sbest = m;
        }
        __syncthreads();
        prev = sbest;
        sum += __uint_as_float((unsigned)(prev >> 32));
    }
    int k = (int)sum;
    if (k < 1)  k = 1;
    if (k > 10) k = 10;

    // phase B: k smallest (cost, idx) — stable argsort tie-break by index
    prev = 0ull;
    for (int t = 0; t < k; t++) {
        unsigned long long best = ~0ull;
#pragma unroll
        for (int j = 0; j < 6; j++) {
            unsigned long long key =
                ((unsigned long long)kcst[j] << 32) | (unsigned)(tid + j * 256);
            if (key > prev && key < best) best = key;
        }
#pragma unroll
        for (int o = 16; o > 0; o >>= 1) {
            unsigned long long oth = __shfl_xor_sync(0xffffffffu, best, o);
            if (oth < best) best = oth;
        }
        if (lane == 0) swp[wid] = best;
        __syncthreads();
        if (tid == 0) {
            unsigned long long m = swp[0];
#pragma unroll
            for (int w2 = 1; w2 < 8; w2++) if (swp[w2] < m) m = swp[w2];
            sbest = m;
            int i = (int)(unsigned)(m & 0xFFFFFFFFull);
            if (m != ~0ull && i < N) {
                int g = bg - b * GG;
                int a = d_fgidx[b * SP + i];
                atomicOr(&d_match[b * AA + a], 1ull << g);
            }
        }
        __syncthreads();
        prev = sbest;
    }
}

// ---------------- block reduction helper ----------------
__device__ __forceinline__ float blockSum(float v, float* s) {
    int tid = threadIdx.x;
#pragma unroll
    for (int o = 16; o > 0; o >>= 1) v += __shfl_xor_sync(0xffffffffu, v, o);
    if ((tid & 31) == 0) s[tid >> 5] = v;
    __syncthreads();
    float r = 0.0f;
    if (tid < (blockDim.x >> 5)) r = s[tid];
#pragma unroll
    for (int o = 4; o > 0; o >>= 1) r += __shfl_xor_sync(0xffffffffu, r, o);
    __syncthreads();
    return r;   // valid in thread 0
}

// ---------------- kernel 4: obj BCE over all anchors + matched compaction ---
__global__ void k_obj(const float* __restrict__ outp) {
    __shared__ float s[8];
    int b = blockIdx.y;
    int a = blockIdx.x * blockDim.x + threadIdx.x;
    float vo = 0.0f, vf = 0.0f;
    if (a < AA) {
        unsigned long long m = d_match[b * AA + a];
        float x = outp[(size_t)(b * AA + a) * ROW + 4];
        float fg = m ? 1.0f : 0.0f;
        vo = fmaxf(x, 0.0f) - x * fg + __logf(1.0f + __expf(-fabsf(x)));
        if (m) {
            vf = 1.0f;
            int pos = atomicAdd(&d_mcnt[b], 1);
            if (pos < MM) d_midx[b * MM + pos] = a;
        }
    }
    float r;
    r = blockSum(vo, s); if (threadIdx.x == 0) atomicAdd(&d_acc[1], (double)r);
    r = blockSum(vf, s); if (threadIdx.x == 0) atomicAdd(&d_acc[4], (double)r);
}

// ---------------- kernel 5: heavy losses on matched anchors only ------------
__global__ void __launch_bounds__(128) k_fgloss(const float* __restrict__ outp,
                                                const float* __restrict__ orig,
                                                const float* __restrict__ labels,
                                                const float* __restrict__ xsA,
                                                const float* __restrict__ ysA,
                                                const float* __restrict__ stA) {
    __shared__ float s[8];
    int b = blockIdx.y;
    int j = blockIdx.x * 128 + threadIdx.x;
    float v_iou = 0.0f, v_cls = 0.0f, v_l1 = 0.0f;
    int mc2 = d_mcnt[b]; if (mc2 > MM) mc2 = MM;
    if (j < mc2) {
        int a = d_midx[b * MM + j];
        unsigned long long m = d_match[b * AA + a];
        int i = d_inv[b * AA + a];
        int mg;
        if (__popcll(m) > 1) {
            float best = FLT_MAX; mg = 0;
            for (int g = 0; g < GG; g++) {
                float c = d_cost[(size_t)(b * GG + g) * SP + i];
                if (c < best) { best = c; mg = g; }
            }
        } else {
            mg = __ffsll((long long)m) - 1;
        }
        const float* L = labels + (b * GG + mg) * 5;
        int   mc = (int)L[0];
        float gxv = L[1], gyv = L[2], gwv = L[3], ghv = L[4];

        const float* o = outp + (size_t)(b * AA + a) * ROW;
        float bx = o[0], by = o[1], bw = o[2], bh = o[3];
        float tlx = fmaxf(bx - bw * 0.5f, gxv - gwv * 0.5f);
        float tly = fmaxf(by - bh * 0.5f, gyv - ghv * 0.5f);
        float brx = fminf(bx + bw * 0.5f, gxv + gwv * 0.5f);
        float bry = fminf(by + bh * 0.5f, gyv + ghv * 0.5f);
        float inter = (tlx < brx && tly < bry) ? (brx - tlx) * (bry - tly) : 0.0f;
        float pred_iou = inter / (bw * bh + gwv * ghv - inter);
        float iou      = inter / (bw * bh + gwv * ghv - inter + 1e-16f);
        v_iou = 1.0f - iou * iou;

        float cl = 0.0f;
#pragma unroll 8
        for (int c = 0; c < CC; c++) {
            float xl = o[5 + c];
            float t  = (c == mc) ? pred_iou : 0.0f;
            cl += fmaxf(xl, 0.0f) - xl * t + log1pf(expf(-fabsf(xl)));
        }
        v_cls = cl;

        float st = stA[a];
        float t0 = gxv / st - xsA[a];
        float t1 = gyv / st - ysA[a];
        float t2 = logf(gwv / st + 1e-8f);
        float t3 = logf(ghv / st + 1e-8f);
        const float* op = orig + (size_t)(b * AA + a) * 4;
        v_l1 = fabsf(op[0] - t0) + fabsf(op[1] - t1) +
               fabsf(op[2] - t2) + fabsf(op[3] - t3);
    }
    float r;
    r = blockSum(v_iou, s); if (threadIdx.x == 0) atomicAdd(&d_acc[0], (double)r);
    r = blockSum(v_cls, s); if (threadIdx.x == 0) atomicAdd(&d_acc[2], (double)r);
    r = blockSum(v_l1,  s); if (threadIdx.x == 0) atomicAdd(&d_acc[3], (double)r);
}

// ---------------- kernel 6: finalize ----------------
__global__ void k_final(float* out) {
    double nfg = d_acc[4];
    if (nfg < 1.0) nfg = 1.0;
    float liou = (float)(5.0 * d_acc[0] / nfg);
    float lobj = (float)(d_acc[1] / nfg);
    float lcls = (float)(d_acc[2] / nfg);
    float ll1  = (float)(d_acc[3] / nfg);
    out[0] = liou + lobj + lcls + ll1;
    out[1] = liou;
    out[2] = lobj;
    out[3] = lcls;
    out[4] = ll1;
    out[5] = (float)(d_acc[4] / (double)(BB * GG));
}

// ---------------- launch ----------------
extern "C" void kernel_launch(void* const* d_in, const int* in_sizes, int n_in,
                              void* d_out, int out_size) {
    const float* outputs = (const float*)d_in[0];
    const float* origin  = (const float*)d_in[1];
    const float* labels  = (const float*)d_in[2];
    const float* xs      = (const float*)d_in[3];
    const float* ys      = (const float*)d_in[4];
    const float* st      = (const float*)d_in[5];

    k_scan<<<BB, 1024>>>(labels);
    k_cost2<<<dim3(SP / 16, BB), 128>>>(outputs, labels);
    k_select<<<BB * GG, 256>>>();
    k_obj<<<dim3((AA + 255) / 256, BB), 256>>>(outputs);
    k_fgloss<<<dim3(MM / 128, BB), 128>>>(outputs, origin, labels, xs, ys, st);
    k_final<<<1, 1>>>((float*)d_out);
}

// round 7
// speedup vs baseline: 1.2917x; 1.2917x over previous
#include <cuda_runtime.h>
#include <math.h>
#include <float.h>

#define BB 32
#define AA 8400
#define GG 40
#define CC 80
#define ROW 85
#define SP 1536      // max candidates per batch (row stride); true bound ~1080
#define MM 512       // max matched anchors per batch

// ---------------- scratch (device globals; no allocation) ----------------
__device__ unsigned long long d_match[BB * AA];
__device__ unsigned long long d_inin [BB * AA];
__device__ unsigned long long d_cinin[BB * SP];
__device__ int    d_fgidx[BB * SP];
__device__ int    d_inv  [BB * AA];
__device__ int    d_fgcnt[BB];
__device__ int    d_mcnt [BB];
__device__ int    d_midx [BB * MM];
__device__ float  d_cost[(size_t)BB * GG * SP];
__device__ float  d_iou [(size_t)BB * GG * SP];
__device__ double d_acc[6];
// compact per-candidate SoA
__device__ float  d_cx1[BB * SP], d_cy1[BB * SP], d_cx2[BB * SP], d_cy2[BB * SP];
__device__ float  d_car[BB * SP], d_cobj[BB * SP], d_suml[BB * SP];

// ---------------- kernel 1: analytic in-region mask + init ----------------
// One thread per (b, anchor). Computes the 40-bit mask directly (no atomics,
// no pre-zeroing), zeroes d_match, inits counters.
__global__ void k_isin(const float* __restrict__ labels) {
    __shared__ float sgx[GG], sgy[GG];
    int b = blockIdx.y;
    int tid = threadIdx.x;
    if (tid < GG) {
        sgx[tid] = labels[(b * GG + tid) * 5 + 1];
        sgy[tid] = labels[(b * GG + tid) * 5 + 2];
    }
    if (blockIdx.x == 0 && tid == 0) d_mcnt[b] = 0;
    if (blockIdx.x == 0 && b == 0 && tid < 6) d_acc[tid] = 0.0;
    __syncthreads();
    int a = blockIdx.x * blockDim.x + tid;
    if (a >= AA) return;
    float s; int n, rel;
    if (a < 6400)      { s = 8.0f;  n = 80; rel = a;        }
    else if (a < 8000) { s = 16.0f; n = 40; rel = a - 6400; }
    else               { s = 32.0f; n = 20; rel = a - 8000; }
    float xc = ((float)(rel % n) + 0.5f) * s;
    float yc = ((float)(rel / n) + 0.5f) * s;
    float r  = 1.5f * s;
    unsigned long long m = 0ull;
#pragma unroll 8
    for (int g = 0; g < GG; g++) {
        // exactly min(dl,dr,dt,db) > 0 in f32
        bool in = (xc > sgx[g] - r) && (xc < sgx[g] + r) &&
                  (yc > sgy[g] - r) && (yc < sgy[g] + r);
        if (in) m |= (1ull << g);
    }
    d_inin [b * AA + a] = m;
    d_match[b * AA + a] = 0ull;
}

// ---------------- kernel 2: ordered compaction (wide warp-ballot scan) -------
// One block per batch, 1024 threads = 32 warps; warp w covers anchors
// [w*263, w*263+263) in 9 ballot iterations.
__global__ void __launch_bounds__(1024) k_scan() {
    __shared__ int wcnt[32];
    int b = blockIdx.x;
    int tid = threadIdx.x, wid = tid >> 5, lane = tid & 31;
    const int CH = 263;
    int base = wid * CH;
    int cnt = 0;
#pragma unroll
    for (int k = 0; k < 9; k++) {
        int loc = k * 32 + lane;
        int a = base + loc;
        bool p = (loc < CH) && (a < AA) && (d_inin[b * AA + a] != 0ull);
        cnt += __popc(__ballot_sync(0xffffffffu, p));
    }
    if (lane == 0) wcnt[wid] = cnt;
    __syncthreads();
    if (wid == 0) {               // inclusive scan of 32 warp counts
        int v = wcnt[lane];
#pragma unroll
        for (int o = 1; o < 32; o <<= 1) {
            int u = __shfl_up_sync(0xffffffffu, v, o);
            if (lane >= o) v += u;
        }
        wcnt[lane] = v;
    }
    __syncthreads();
    if (tid == 0) {
        int tot = wcnt[31];
        d_fgcnt[b] = tot < SP ? tot : SP;
    }
    int pos = wcnt[wid] - cnt;    // exclusive warp offset
#pragma unroll
    for (int k = 0; k < 9; k++) {
        int loc = k * 32 + lane;
        int a = base + loc;
        bool p = (loc < CH) && (a < AA) && (d_inin[b * AA + a] != 0ull);
        unsigned bal = __ballot_sync(0xffffffffu, p);
        int my = __popc(bal & ((1u << lane) - 1u));
        if (p && pos + my < SP) {
            d_fgidx[b * SP + pos + my] = a;
            d_inv  [b * AA + a]        = pos + my;
        }
        pos += __popc(bal);
    }
}

// ---------------- kernel 3a: candidate prep + suml (16 lanes / candidate) ----
// 128 threads = 4 warps; each warp covers 2 candidates -> 8 candidates/block.
__global__ void __launch_bounds__(128) k_prep(const float* __restrict__ outp) {
    int b   = blockIdx.y;
    int cnt = d_fgcnt[b];
    if (blockIdx.x * 8 >= cnt) return;               // whole-block uniform exit
    int tid  = threadIdx.x;
    int lane = tid & 31, warp = tid >> 5;
    int grp  = lane >> 4, sub = lane & 15;
    int i    = blockIdx.x * 8 + warp * 2 + grp;
    bool valid = (i < cnt);
    int ic = valid ? i : (cnt - 1);                  // clamp; full-warp shfl safe
    int a  = d_fgidx[b * SP + ic];
    const float* o = outp + (size_t)(b * AA + a) * ROW;
    float obj = o[4];
    // product of (1 - sqrt(cls*obj)) over this lane's 5 classes
    float prod = 1.0f;
#pragma unroll
    for (int c = 0; c < 5; c++) {
        float x = o[5 + sub * 5 + c] * obj;
        prod *= (1.0f - x * rsqrtf(x));
    }
    float l = __logf(prod);
    l += __shfl_xor_sync(0xffffffffu, l, 1);
    l += __shfl_xor_sync(0xffffffffu, l, 2);
    l += __shfl_xor_sync(0xffffffffu, l, 4);
    l += __shfl_xor_sync(0xffffffffu, l, 8);
    if (sub == 0 && valid) {
        float bx = o[0], by = o[1], bw = o[2], bh = o[3];
        int idx = b * SP + i;
        d_cx1[idx] = bx - bw * 0.5f; d_cy1[idx] = by - bh * 0.5f;
        d_cx2[idx] = bx + bw * 0.5f; d_cy2[idx] = by + bh * 0.5f;
        d_car[idx] = bw * bh;
        d_cobj[idx] = obj;
        d_suml[idx] = l;
        d_cinin[idx] = d_inin[b * AA + a];
    }
}

// ---------------- kernel 3b: pairwise iou + cost (thread per (b,g,i)) --------
__global__ void __launch_bounds__(128) k_pair(const float* __restrict__ outp,
                                              const float* __restrict__ labels) {
    int bg = blockIdx.y;
    int b = bg / GG, g = bg % GG;
    int cnt = d_fgcnt[b];
    int i = blockIdx.x * 128 + threadIdx.x;
    if (i >= cnt) return;
    const float* L = labels + (b * GG + g) * 5;      // uniform: broadcast loads
    int   gc  = (int)L[0];
    float gxv = L[1], gyv = L[2], gwv = L[3], ghv = L[4];
    float qx1 = gxv - gwv * 0.5f, qx2 = gxv + gwv * 0.5f;
    float qy1 = gyv - ghv * 0.5f, qy2 = gyv + ghv * 0.5f;
    float qar = gwv * ghv;

    int idx = b * SP + i;
    float w = fminf(d_cx2[idx], qx2) - fmaxf(d_cx1[idx], qx1);
    float h = fminf(d_cy2[idx], qy2) - fmaxf(d_cy1[idx], qy1);
    float inter = fmaxf(w, 0.0f) * fmaxf(h, 0.0f);
    float den = d_car[idx] + qar - inter;
    // FMA-pipe reciprocal (bit-trick + 2 Newton); den >= 1 always here
    float y = __uint_as_float(0x7EF311C3u - __float_as_uint(den));
    y = y * (2.0f - den * y);
    y = y * (2.0f - den * y);
    float iou = inter * y;
    size_t off = (size_t)bg * SP + i;
    d_iou[off] = iou;
    float cost = FLT_MAX;
    if ((d_cinin[idx] >> g) & 1ull) {
        int a = d_fgidx[b * SP + i];
        float xg = outp[(size_t)(b * AA + a) * ROW + 5 + gc] * d_cobj[idx];
        float pg = xg * rsqrtf(xg);
        cost = -d_suml[idx] - (0.5f * __logf(xg) - __logf(1.0f - pg))
               - 3.0f * __logf(iou + 1e-8f);
    }
    d_cost[off] = cost;
}

// ---------------- kernel 4: block-per-(b,g) dynamic_k + stable top-k ----------
__global__ void __launch_bounds__(256) k_select() {
    __shared__ unsigned long long swp[8];
    __shared__ unsigned long long sbest;
    int bg = blockIdx.x;
    int b  = bg / GG;
    int tid = threadIdx.x, lane = tid & 31, wid = tid >> 5;
    int N = d_fgcnt[b];
    const float* irow = d_iou  + (size_t)bg * SP;
    const float* crow = d_cost + (size_t)bg * SP;

    unsigned kiou[6], kcst[6];
#pragma unroll
    for (int j = 0; j < 6; j++) {
        int i = tid + j * 256;
        bool v = (i < N);
        kiou[j] = v ? __float_as_uint(irow[i]) : 0u;
        unsigned cb = v ? __float_as_uint(crow[i]) : 0x7F800000u;
        kcst[j] = (cb & 0x80000000u) ? ~cb : (cb | 0x80000000u);
    }

    // phase A: sum of top-10 iou values
    float sum = 0.0f;
    unsigned long long prev = ~0ull;
    for (int t = 0; t < 10; t++) {
        unsigned long long best = 0ull;
#pragma unroll
        for (int j = 0; j < 6; j++) {
            unsigned long long key =
                ((unsigned long long)kiou[j] << 32) | (unsigned)(tid + j * 256);
            if (key < prev && key > best) best = key;
        }
#pragma unroll
        for (int o = 16; o > 0; o >>= 1) {
            unsigned long long oth = __shfl_xor_sync(0xffffffffu, best, o);
            if (oth > best) best = oth;
        }
        if (lane == 0) swp[wid] = best;
        __syncthreads();
        if (tid == 0) {
            unsigned long long m = swp[0];
#pragma unroll
            for (int w2 = 1; w2 < 8; w2++) if (swp[w2] > m) m = swp[w2];
            sbest = m;
        }
        __syncthreads();
        prev = sbest;
        sum += __uint_as_float((unsigned)(prev >> 32));
    }
    int k = (int)sum;
    if (k < 1)  k = 1;
    if (k > 10) k = 10;

    // phase B: k smallest (cost, idx) — stable argsort tie-break by index
    prev = 0ull;
    for (int t = 0; t < k; t++) {
        unsigned long long best = ~0ull;
#pragma unroll
        for (int j = 0; j < 6; j++) {
            unsigned long long key =
                ((unsigned long long)kcst[j] << 32) | (unsigned)(tid + j * 256);
            if (key > prev && key < best) best = key;
        }
#pragma unroll
        for (int o = 16; o > 0; o >>= 1) {
            unsigned long long oth = __shfl_xor_sync(0xffffffffu, best, o);
            if (oth < best) best = oth;
        }
        if (lane == 0) swp[wid] = best;
        __syncthreads();
        if (tid == 0) {
            unsigned long long m = swp[0];
#pragma unroll
            for (int w2 = 1; w2 < 8; w2++) if (swp[w2] < m) m = swp[w2];
            sbest = m;
            int i = (int)(unsigned)(m & 0xFFFFFFFFull);
            if (m != ~0ull && i < N) {
                int g = bg - b * GG;
                int a = d_fgidx[b * SP + i];
                atomicOr(&d_match[b * AA + a], 1ull << g);
            }
        }
        __syncthreads();
        prev = sbest;
    }
}

// ---------------- block reduction helper ----------------
__device__ __forceinline__ float blockSum(float v, float* s) {
    int tid = threadIdx.x;
#pragma unroll
    for (int o = 16; o > 0; o >>= 1) v += __shfl_xor_sync(0xffffffffu, v, o);
    if ((tid & 31) == 0) s[tid >> 5] = v;
    __syncthreads();
    float r = 0.0f;
    if (tid < (blockDim.x >> 5)) r = s[tid];
#pragma unroll
    for (int o = 4; o > 0; o >>= 1) r += __shfl_xor_sync(0xffffffffu, r, o);
    __syncthreads();
    return r;   // valid in thread 0
}

// ---------------- kernel 5: obj BCE over all anchors + matched compaction ----
__global__ void k_obj(const float* __restrict__ outp) {
    __shared__ float s[8];
    int b = blockIdx.y;
    int a = blockIdx.x * blockDim.x + threadIdx.x;
    float vo = 0.0f, vf = 0.0f;
    if (a < AA) {
        unsigned long long m = d_match[b * AA + a];
        float x = outp[(size_t)(b * AA + a) * ROW + 4];
        float fg = m ? 1.0f : 0.0f;
        vo = fmaxf(x, 0.0f) - x * fg + __logf(1.0f + __expf(-fabsf(x)));
        if (m) {
            vf = 1.0f;
            int pos = atomicAdd(&d_mcnt[b], 1);
            if (pos < MM) d_midx[b * MM + pos] = a;
        }
    }
    float r;
    r = blockSum(vo, s); if (threadIdx.x == 0) atomicAdd(&d_acc[1], (double)r);
    r = blockSum(vf, s); if (threadIdx.x == 0) atomicAdd(&d_acc[4], (double)r);
}

// ---------------- kernel 6: heavy losses on matched anchors only -------------
__global__ void __launch_bounds__(128) k_fgloss(const float* __restrict__ outp,
                                                const float* __restrict__ orig,
                                                const float* __restrict__ labels,
                                                const float* __restrict__ xsA,
                                                const float* __restrict__ ysA,
                                                const float* __restrict__ stA) {
    __shared__ float s[8];
    int b = blockIdx.y;
    int j = blockIdx.x * 128 + threadIdx.x;
    float v_iou = 0.0f, v_cls = 0.0f, v_l1 = 0.0f;
    int mc2 = d_mcnt[b]; if (mc2 > MM) mc2 = MM;
    if (j < mc2) {
        int a = d_midx[b * MM + j];
        unsigned long long m = d_match[b * AA + a];
        int i = d_inv[b * AA + a];
        int mg;
        if (__popcll(m) > 1) {
            float best = FLT_MAX; mg = 0;
            for (int g = 0; g < GG; g++) {
                float c = d_cost[(size_t)(b * GG + g) * SP + i];
                if (c < best) { best = c; mg = g; }
            }
        } else {
            mg = __ffsll((long long)m) - 1;
        }
        const float* L = labels + (b * GG + mg) * 5;
        int   mc = (int)L[0];
        float gxv = L[1], gyv = L[2], gwv = L[3], ghv = L[4];

        const float* o = outp + (size_t)(b * AA + a) * ROW;
        float bx = o[0], by = o[1], bw = o[2], bh = o[3];
        float tlx = fmaxf(bx - bw * 0.5f, gxv - gwv * 0.5f);
        float tly = fmaxf(by - bh * 0.5f, gyv - ghv * 0.5f);
        float brx = fminf(bx + bw * 0.5f, gxv + gwv * 0.5f);
        float bry = fminf(by + bh * 0.5f, gyv + ghv * 0.5f);
        float inter = (tlx < brx && tly < bry) ? (brx - tlx) * (bry - tly) : 0.0f;
        float pred_iou = inter / (bw * bh + gwv * ghv - inter);
        float iou      = inter / (bw * bh + gwv * ghv - inter + 1e-16f);
        v_iou = 1.0f - iou * iou;

        float cl = 0.0f;
#pragma unroll 8
        for (int c = 0; c < CC; c++) {
            float xl = o[5 + c];
            float t  = (c == mc) ? pred_iou : 0.0f;
            cl += fmaxf(xl, 0.0f) - xl * t + log1pf(expf(-fabsf(xl)));
        }
        v_cls = cl;

        float st = stA[a];
        float t0 = gxv / st - xsA[a];
        float t1 = gyv / st - ysA[a];
        float t2 = logf(gwv / st + 1e-8f);
        float t3 = logf(ghv / st + 1e-8f);
        const float* op = orig + (size_t)(b * AA + a) * 4;
        v_l1 = fabsf(op[0] - t0) + fabsf(op[1] - t1) +
               fabsf(op[2] - t2) + fabsf(op[3] - t3);
    }
    float r;
    r = blockSum(v_iou, s); if (threadIdx.x == 0) atomicAdd(&d_acc[0], (double)r);
    r = blockSum(v_cls, s); if (threadIdx.x == 0) atomicAdd(&d_acc[2], (double)r);
    r = blockSum(v_l1,  s); if (threadIdx.x == 0) atomicAdd(&d_acc[3], (double)r);
}

// ---------------- kernel 7: finalize ----------------
__global__ void k_final(float* out) {
    double nfg = d_acc[4];
    if (nfg < 1.0) nfg = 1.0;
    float liou = (float)(5.0 * d_acc[0] / nfg);
    float lobj = (float)(d_acc[1] / nfg);
    float lcls = (float)(d_acc[2] / nfg);
    float ll1  = (float)(d_acc[3] / nfg);
    out[0] = liou + lobj + lcls + ll1;
    out[1] = liou;
    out[2] = lobj;
    out[3] = lcls;
    out[4] = ll1;
    out[5] = (float)(d_acc[4] / (double)(BB * GG));
}

// ---------------- launch ----------------
extern "C" void kernel_launch(void* const* d_in, const int* in_sizes, int n_in,
                              void* d_out, int out_size) {
    const float* outputs = (const float*)d_in[0];
    const float* origin  = (const float*)d_in[1];
    const float* labels  = (const float*)d_in[2];
    const float* xs      = (const float*)d_in[3];
    const float* ys      = (const float*)d_in[4];
    const float* st      = (const float*)d_in[5];

    k_isin<<<dim3((AA + 255) / 256, BB), 256>>>(labels);
    k_scan<<<BB, 1024>>>();
    k_prep<<<dim3(SP / 8, BB), 128>>>(outputs);
    k_pair<<<dim3(SP / 128, BB * GG), 128>>>(outputs, labels);
    k_select<<<BB * GG, 256>>>();
    k_obj<<<dim3((AA + 255) / 256, BB), 256>>>(outputs);
    k_fgloss<<<dim3(MM / 128, BB), 128>>>(outputs, origin, labels, xs, ys, st);
    k_final<<<1, 1>>>((float*)d_out);
}

// round 8
// speedup vs baseline: 1.3212x; 1.0228x over previous
#include <cuda_runtime.h>
#include <math.h>
#include <float.h>

#define BB 32
#define AA 8400
#define GG 40
#define CC 80
#define ROW 85
#define SP 1536      // max candidates per batch (row stride); true bound ~1080
#define MM 512       // max matched anchors per batch

// ---------------- scratch (device globals; zero-init at load) ----------------
__device__ unsigned long long d_match[BB * AA];
__device__ unsigned long long d_inin [BB * AA];
__device__ unsigned long long d_cinin[BB * SP];
__device__ int    d_fgidx[BB * SP];
__device__ int    d_inv  [BB * AA];
__device__ int    d_fgcnt[BB];
__device__ int    d_mcnt [BB];     // zeroed by k_final each run
__device__ int    d_midx [BB * MM];
__device__ float  d_cost[(size_t)BB * GG * SP];
__device__ float  d_iou [(size_t)BB * GG * SP];
__device__ double d_acc[6];        // zeroed by k_final each run
__device__ float4 d_cbox [BB * SP];   // x1,y1,x2,y2
__device__ float4 d_cmeta[BB * SP];   // area, obj, suml, -

// ---------------- block reduction helper ----------------
__device__ __forceinline__ float blockSum(float v, float* s) {
    int tid = threadIdx.x;
#pragma unroll
    for (int o = 16; o > 0; o >>= 1) v += __shfl_xor_sync(0xffffffffu, v, o);
    if ((tid & 31) == 0) s[tid >> 5] = v;
    __syncthreads();
    float r = 0.0f;
    if (tid < (blockDim.x >> 5)) r = s[tid];
#pragma unroll
    for (int o = 4; o > 0; o >>= 1) r += __shfl_xor_sync(0xffffffffu, r, o);
    __syncthreads();
    return r;   // valid in thread 0
}

// ---------------- kernel 1: analytic mask + fg-independent obj BCE ----------
// One thread per (b, anchor). Computes the 40-bit in-region mask analytically,
// zeroes d_match, and accumulates sum_all [max(x,0)+log1p(exp(-|x|))].
__global__ void k_isin(const float* __restrict__ labels,
                       const float* __restrict__ outp) {
    __shared__ float sgx[GG], sgy[GG];
    __shared__ float s[8];
    int b = blockIdx.y;
    int tid = threadIdx.x;
    if (tid < GG) {
        sgx[tid] = labels[(b * GG + tid) * 5 + 1];
        sgy[tid] = labels[(b * GG + tid) * 5 + 2];
    }
    __syncthreads();
    int a = blockIdx.x * blockDim.x + tid;
    float vo = 0.0f;
    if (a < AA) {
        float sc; int n, rel;
        if (a < 6400)      { sc = 8.0f;  n = 80; rel = a;        }
        else if (a < 8000) { sc = 16.0f; n = 40; rel = a - 6400; }
        else               { sc = 32.0f; n = 20; rel = a - 8000; }
        float xc = ((float)(rel % n) + 0.5f) * sc;
        float yc = ((float)(rel / n) + 0.5f) * sc;
        float r  = 1.5f * sc;
        unsigned long long m = 0ull;
#pragma unroll 8
        for (int g = 0; g < GG; g++) {
            bool in = (xc > sgx[g] - r) && (xc < sgx[g] + r) &&
                      (yc > sgy[g] - r) && (yc < sgy[g] + r);
            if (in) m |= (1ull << g);
        }
        d_inin [b * AA + a] = m;
        d_match[b * AA + a] = 0ull;
        float x = outp[(size_t)(b * AA + a) * ROW + 4];
        vo = fmaxf(x, 0.0f) + __logf(1.0f + __expf(-fabsf(x)));
    }
    float r = blockSum(vo, s);
    if (tid == 0) atomicAdd(&d_acc[1], (double)r);
}

// ---------------- kernel 2: ordered compaction (wide warp-ballot scan) -------
__global__ void __launch_bounds__(1024) k_scan() {
    __shared__ int wcnt[32];
    int b = blockIdx.x;
    int tid = threadIdx.x, wid = tid >> 5, lane = tid & 31;
    const int CH = 263;
    int base = wid * CH;
    int cnt = 0;
#pragma unroll
    for (int k = 0; k < 9; k++) {
        int loc = k * 32 + lane;
        int a = base + loc;
        bool p = (loc < CH) && (a < AA) && (d_inin[b * AA + a] != 0ull);
        cnt += __popc(__ballot_sync(0xffffffffu, p));
    }
    if (lane == 0) wcnt[wid] = cnt;
    __syncthreads();
    if (wid == 0) {               // inclusive scan of 32 warp counts
        int v = wcnt[lane];
#pragma unroll
        for (int o = 1; o < 32; o <<= 1) {
            int u = __shfl_up_sync(0xffffffffu, v, o);
            if (lane >= o) v += u;
        }
        wcnt[lane] = v;
    }
    __syncthreads();
    if (tid == 0) {
        int tot = wcnt[31];
        d_fgcnt[b] = tot < SP ? tot : SP;
    }
    int pos = wcnt[wid] - cnt;    // exclusive warp offset
#pragma unroll
    for (int k = 0; k < 9; k++) {
        int loc = k * 32 + lane;
        int a = base + loc;
        bool p = (loc < CH) && (a < AA) && (d_inin[b * AA + a] != 0ull);
        unsigned bal = __ballot_sync(0xffffffffu, p);
        int my = __popc(bal & ((1u << lane) - 1u));
        if (p && pos + my < SP) {
            d_fgidx[b * SP + pos + my] = a;
            d_inv  [b * AA + a]        = pos + my;
        }
        pos += __popc(bal);
    }
}

// ---------------- kernel 3a: candidate prep + suml (16 lanes / candidate) ----
__global__ void __launch_bounds__(128) k_prep(const float* __restrict__ outp) {
    int b   = blockIdx.y;
    int cnt = d_fgcnt[b];
    if (blockIdx.x * 8 >= cnt) return;               // whole-block uniform exit
    int tid  = threadIdx.x;
    int lane = tid & 31, warp = tid >> 5;
    int grp  = lane >> 4, sub = lane & 15;
    int i    = blockIdx.x * 8 + warp * 2 + grp;
    bool valid = (i < cnt);
    int ic = valid ? i : (cnt - 1);                  // clamp; full-warp shfl safe
    int a  = d_fgidx[b * SP + ic];
    const float* o = outp + (size_t)(b * AA + a) * ROW;
    float obj = o[4];
    float prod = 1.0f;
#pragma unroll
    for (int c = 0; c < 5; c++) {
        float x = o[5 + sub * 5 + c] * obj;
        prod *= (1.0f - x * rsqrtf(x));
    }
    float l = __logf(prod);
    l += __shfl_xor_sync(0xffffffffu, l, 1);
    l += __shfl_xor_sync(0xffffffffu, l, 2);
    l += __shfl_xor_sync(0xffffffffu, l, 4);
    l += __shfl_xor_sync(0xffffffffu, l, 8);
    if (sub == 0 && valid) {
        float bx = o[0], by = o[1], bw = o[2], bh = o[3];
        int idx = b * SP + i;
        d_cbox [idx] = make_float4(bx - bw * 0.5f, by - bh * 0.5f,
                                   bx + bw * 0.5f, by + bh * 0.5f);
        d_cmeta[idx] = make_float4(bw * bh, obj, l, 0.0f);
        d_cinin[idx] = d_inin[b * AA + a];
    }
}

// ---------------- kernel 3b: pairwise iou + cost (thread per (b,g,i)) --------
__global__ void __launch_bounds__(128) k_pair(const float* __restrict__ outp,
                                              const float* __restrict__ labels) {
    int bg = blockIdx.y;
    int b = bg / GG, g = bg % GG;
    int cnt = d_fgcnt[b];
    int i = blockIdx.x * 128 + threadIdx.x;
    if (i >= cnt) return;
    const float* L = labels + (b * GG + g) * 5;      // uniform: broadcast loads
    int   gc  = (int)L[0];
    float gxv = L[1], gyv = L[2], gwv = L[3], ghv = L[4];
    float qx1 = gxv - gwv * 0.5f, qx2 = gxv + gwv * 0.5f;
    float qy1 = gyv - ghv * 0.5f, qy2 = gyv + ghv * 0.5f;
    float qar = gwv * ghv;

    int idx = b * SP + i;
    float4 box  = d_cbox [idx];
    float4 meta = d_cmeta[idx];
    unsigned long long inin = d_cinin[idx];
    float w = fminf(box.z, qx2) - fmaxf(box.x, qx1);
    float h = fminf(box.w, qy2) - fmaxf(box.y, qy1);
    float inter = fmaxf(w, 0.0f) * fmaxf(h, 0.0f);
    float den = meta.x + qar - inter;
    // FMA-pipe reciprocal (bit-trick + 2 Newton); den >= 1 always here
    float y = __uint_as_float(0x7EF311C3u - __float_as_uint(den));
    y = y * (2.0f - den * y);
    y = y * (2.0f - den * y);
    float iou = inter * y;
    size_t off = (size_t)bg * SP + i;
    d_iou[off] = iou;
    float cost = FLT_MAX;
    if ((inin >> g) & 1ull) {
        int a = d_fgidx[b * SP + i];
        float xg = outp[(size_t)(b * AA + a) * ROW + 5 + gc] * meta.y;
        float pg = xg * rsqrtf(xg);
        cost = -meta.z - (0.5f * __logf(xg) - __logf(1.0f - pg))
               - 3.0f * __logf(iou + 1e-8f);
    }
    d_cost[off] = cost;
}

// ---------------- kernel 4: block-per-(b,g) dynamic_k + stable top-k ---------
// Also compacts newly-matched anchors (first atomicOr setter appends to midx).
__global__ void __launch_bounds__(256) k_select() {
    __shared__ unsigned long long swp[8];
    __shared__ unsigned long long sbest;
    int bg = blockIdx.x;
    int b  = bg / GG;
    int tid = threadIdx.x, lane = tid & 31, wid = tid >> 5;
    int N = d_fgcnt[b];
    const float* irow = d_iou  + (size_t)bg * SP;
    const float* crow = d_cost + (size_t)bg * SP;

    unsigned kiou[6], kcst[6];
#pragma unroll
    for (int j = 0; j < 6; j++) {
        int i = tid + j * 256;
        bool v = (i < N);
        kiou[j] = v ? __float_as_uint(irow[i]) : 0u;
        unsigned cb = v ? __float_as_uint(crow[i]) : 0x7F800000u;
        kcst[j] = (cb & 0x80000000u) ? ~cb : (cb | 0x80000000u);
    }

    // phase A: sum of top-10 iou values
    float sum = 0.0f;
    unsigned long long prev = ~0ull;
    for (int t = 0; t < 10; t++) {
        unsigned long long best = 0ull;
#pragma unroll
        for (int j = 0; j < 6; j++) {
            unsigned long long key =
                ((unsigned long long)kiou[j] << 32) | (unsigned)(tid + j * 256);
            if (key < prev && key > best) best = key;
        }
#pragma unroll
        for (int o = 16; o > 0; o >>= 1) {
            unsigned long long oth = __shfl_xor_sync(0xffffffffu, best, o);
            if (oth > best) best = oth;
        }
        if (lane == 0) swp[wid] = best;
        __syncthreads();
        if (tid == 0) {
            unsigned long long m = swp[0];
#pragma unroll
            for (int w2 = 1; w2 < 8; w2++) if (swp[w2] > m) m = swp[w2];
            sbest = m;
        }
        __syncthreads();
        prev = sbest;
        sum += __uint_as_float((unsigned)(prev >> 32));
    }
    int k = (int)sum;
    if (k < 1)  k = 1;
    if (k > 10) k = 10;

    // phase B: k smallest (cost, idx) — stable argsort tie-break by index
    prev = 0ull;
    for (int t = 0; t < k; t++) {
        unsigned long long best = ~0ull;
#pragma unroll
        for (int j = 0; j < 6; j++) {
            unsigned long long key =
                ((unsigned long long)kcst[j] << 32) | (unsigned)(tid + j * 256);
            if (key > prev && key < best) best = key;
        }
#pragma unroll
        for (int o = 16; o > 0; o >>= 1) {
            unsigned long long oth = __shfl_xor_sync(0xffffffffu, best, o);
            if (oth < best) best = oth;
        }
        if (lane == 0) swp[wid] = best;
        __syncthreads();
        if (tid == 0) {
            unsigned long long m = swp[0];
#pragma unroll
            for (int w2 = 1; w2 < 8; w2++) if (swp[w2] < m) m = swp[w2];
            sbest = m;
            int i = (int)(unsigned)(m & 0xFFFFFFFFull);
            if (m != ~0ull && i < N) {
                int g = bg - b * GG;
                int a = d_fgidx[b * SP + i];
                unsigned long long old =
                    atomicOr(&d_match[b * AA + a], 1ull << g);
                if (old == 0ull) {            // first match -> compact
                    int pos = atomicAdd(&d_mcnt[b], 1);
                    if (pos < MM) d_midx[b * MM + pos] = a;
                }
            }
        }
        __syncthreads();
        prev = sbest;
    }
}

// ---------------- kernel 5: heavy losses on matched anchors only -------------
__global__ void __launch_bounds__(128) k_fgloss(const float* __restrict__ outp,
                                                const float* __restrict__ orig,
                                                const float* __restrict__ labels,
                                                const float* __restrict__ xsA,
                                                const float* __restrict__ ysA,
                                                const float* __restrict__ stA) {
    __shared__ float s[8];
    int b = blockIdx.y;
    int j = blockIdx.x * 128 + threadIdx.x;
    float v_iou = 0.0f, v_cls = 0.0f, v_l1 = 0.0f, v_obj = 0.0f;
    int mc2 = d_mcnt[b]; if (mc2 > MM) mc2 = MM;
    if (j < mc2) {
        int a = d_midx[b * MM + j];
        unsigned long long m = d_match[b * AA + a];
        int i = d_inv[b * AA + a];
        int mg;
        if (__popcll(m) > 1) {
            float best = FLT_MAX; mg = 0;
            for (int g = 0; g < GG; g++) {
                float c = d_cost[(size_t)(b * GG + g) * SP + i];
                if (c < best) { best = c; mg = g; }
            }
        } else {
            mg = __ffsll((long long)m) - 1;
        }
        const float* L = labels + (b * GG + mg) * 5;
        int   mc = (int)L[0];
        float gxv = L[1], gyv = L[2], gwv = L[3], ghv = L[4];

        const float* o = outp + (size_t)(b * AA + a) * ROW;
        v_obj = -o[4];                       // fg-dependent obj BCE term
        float bx = o[0], by = o[1], bw = o[2], bh = o[3];
        float tlx = fmaxf(bx - bw * 0.5f, gxv - gwv * 0.5f);
        float tly = fmaxf(by - bh * 0.5f, gyv - ghv * 0.5f);
        float brx = fminf(bx + bw * 0.5f, gxv + gwv * 0.5f);
        float bry = fminf(by + bh * 0.5f, gyv + ghv * 0.5f);
        float inter = (tlx < brx && tly < bry) ? (brx - tlx) * (bry - tly) : 0.0f;
        float pred_iou = inter / (bw * bh + gwv * ghv - inter);
        float iou      = inter / (bw * bh + gwv * ghv - inter + 1e-16f);
        v_iou = 1.0f - iou * iou;

        float cl = 0.0f;
#pragma unroll 8
        for (int c = 0; c < CC; c++) {
            float xl = o[5 + c];
            float t  = (c == mc) ? pred_iou : 0.0f;
            cl += fmaxf(xl, 0.0f) - xl * t + log1pf(expf(-fabsf(xl)));
        }
        v_cls = cl;

        float st = stA[a];
        float t0 = gxv / st - xsA[a];
        float t1 = gyv / st - ysA[a];
        float t2 = logf(gwv / st + 1e-8f);
        float t3 = logf(ghv / st + 1e-8f);
        const float* op = orig + (size_t)(b * AA + a) * 4;
        v_l1 = fabsf(op[0] - t0) + fabsf(op[1] - t1) +
               fabsf(op[2] - t2) + fabsf(op[3] - t3);
    }
    float r;
    r = blockSum(v_iou, s); if (threadIdx.x == 0) atomicAdd(&d_acc[0], (double)r);
    r = blockSum(v_obj, s); if (threadIdx.x == 0) atomicAdd(&d_acc[1], (double)r);
    r = blockSum(v_cls, s); if (threadIdx.x == 0) atomicAdd(&d_acc[2], (double)r);
    r = blockSum(v_l1,  s); if (threadIdx.x == 0) atomicAdd(&d_acc[3], (double)r);
}

// ---------------- kernel 6: finalize + reset accumulators for next replay ----
__global__ void k_final(float* out) {
    int tid = threadIdx.x;
    __shared__ int tot_s;
    if (tid == 0) {
        int tot = 0;
        for (int b2 = 0; b2 < BB; b2++) tot += d_mcnt[b2];
        tot_s = tot;
        double nfg = (double)tot;
        if (nfg < 1.0) nfg = 1.0;
        float liou = (float)(5.0 * d_acc[0] / nfg);
        float lobj = (float)(d_acc[1] / nfg);
        float lcls = (float)(d_acc[2] / nfg);
        float ll1  = (float)(d_acc[3] / nfg);
        out[0] = liou + lobj + lcls + ll1;
        out[1] = liou;
        out[2] = lobj;
        out[3] = lcls;
        out[4] = ll1;
        out[5] = (float)(nfg / (double)(BB * GG));
    }
    __syncthreads();
    // reset for next graph replay (globals start zeroed at module load)
    d_mcnt[tid] = 0;
    if (tid < 6) d_acc[tid] = 0.0;
}

// ---------------- launch ----------------
extern "C" void kernel_launch(void* const* d_in, const int* in_sizes, int n_in,
                              void* d_out, int out_size) {
    const float* outputs = (const float*)d_in[0];
    const float* origin  = (const float*)d_in[1];
    const float* labels  = (const float*)d_in[2];
    const float* xs      = (const float*)d_in[3];
    const float* ys      = (const float*)d_in[4];
    const float* st      = (const float*)d_in[5];

    k_isin<<<dim3((AA + 255) / 256, BB), 256>>>(labels, outputs);
    k_scan<<<BB, 1024>>>();
    k_prep<<<dim3(SP / 8, BB), 128>>>(outputs);
    k_pair<<<dim3(SP / 128, BB * GG), 128>>>(outputs, labels);
    k_select<<<BB * GG, 256>>>();
    k_fgloss<<<dim3(MM / 128, BB), 128>>>(outputs, origin, labels, xs, ys, st);
    k_final<<<1, 32>>>((float*)d_out);
}

// round 9
// speedup vs baseline: 1.4487x; 1.0965x over previous
#include <cuda_runtime.h>
#include <math.h>
#include <float.h>

#define BB 32
#define AA 8400
#define GG 40
#define CC 80
#define ROW 85
#define SP 1536      // max candidates per batch (row stride); true bound ~1080
#define MM 512       // max matched anchors per batch

// ---------------- scratch (device globals; zero-init at load) ----------------
__device__ unsigned long long d_match[BB * AA];
__device__ unsigned long long d_inin [BB * AA];
__device__ unsigned long long d_cinin[BB * SP];
__device__ int    d_fgidx[BB * SP];
__device__ int    d_inv  [BB * AA];
__device__ int    d_fgcnt[BB];
__device__ int    d_mcnt [BB];     // zeroed by k_final each run
__device__ int    d_midx [BB * MM];
__device__ float  d_cost[(size_t)BB * GG * SP];
__device__ double d_acc[6];        // zeroed by k_final each run
__device__ float4 d_cbox [BB * SP];   // x1,y1,x2,y2
__device__ float4 d_cmeta[BB * SP];   // area, obj, suml, -

// ---------------- block reduction helper ----------------
__device__ __forceinline__ float blockSum(float v, float* s) {
    int tid = threadIdx.x;
#pragma unroll
    for (int o = 16; o > 0; o >>= 1) v += __shfl_xor_sync(0xffffffffu, v, o);
    if ((tid & 31) == 0) s[tid >> 5] = v;
    __syncthreads();
    float r = 0.0f;
    if (tid < (blockDim.x >> 5)) r = s[tid];
#pragma unroll
    for (int o = 4; o > 0; o >>= 1) r += __shfl_xor_sync(0xffffffffu, r, o);
    __syncthreads();
    return r;   // valid in thread 0
}

// ---------------- kernel 1: analytic mask + fg-independent obj BCE ----------
__global__ void k_isin(const float* __restrict__ labels,
                       const float* __restrict__ outp) {
    __shared__ float sgx[GG], sgy[GG];
    __shared__ float s[8];
    int b = blockIdx.y;
    int tid = threadIdx.x;
    if (tid < GG) {
        sgx[tid] = labels[(b * GG + tid) * 5 + 1];
        sgy[tid] = labels[(b * GG + tid) * 5 + 2];
    }
    __syncthreads();
    int a = blockIdx.x * blockDim.x + tid;
    float vo = 0.0f;
    if (a < AA) {
        float sc; int n, rel;
        if (a < 6400)      { sc = 8.0f;  n = 80; rel = a;        }
        else if (a < 8000) { sc = 16.0f; n = 40; rel = a - 6400; }
        else               { sc = 32.0f; n = 20; rel = a - 8000; }
        float xc = ((float)(rel % n) + 0.5f) * sc;
        float yc = ((float)(rel / n) + 0.5f) * sc;
        float r  = 1.5f * sc;
        unsigned long long m = 0ull;
#pragma unroll 8
        for (int g = 0; g < GG; g++) {
            bool in = (xc > sgx[g] - r) && (xc < sgx[g] + r) &&
                      (yc > sgy[g] - r) && (yc < sgy[g] + r);
            if (in) m |= (1ull << g);
        }
        d_inin [b * AA + a] = m;
        d_match[b * AA + a] = 0ull;
        float x = outp[(size_t)(b * AA + a) * ROW + 4];
        vo = fmaxf(x, 0.0f) + __logf(1.0f + __expf(-fabsf(x)));
    }
    float r = blockSum(vo, s);
    if (tid == 0) atomicAdd(&d_acc[1], (double)r);
}

// ---------------- kernel 2: ordered compaction (wide warp-ballot scan) -------
__global__ void __launch_bounds__(1024) k_scan() {
    __shared__ int wcnt[32];
    int b = blockIdx.x;
    int tid = threadIdx.x, wid = tid >> 5, lane = tid & 31;
    const int CH = 263;
    int base = wid * CH;
    int cnt = 0;
#pragma unroll
    for (int k = 0; k < 9; k++) {
        int loc = k * 32 + lane;
        int a = base + loc;
        bool p = (loc < CH) && (a < AA) && (d_inin[b * AA + a] != 0ull);
        cnt += __popc(__ballot_sync(0xffffffffu, p));
    }
    if (lane == 0) wcnt[wid] = cnt;
    __syncthreads();
    if (wid == 0) {
        int v = wcnt[lane];
#pragma unroll
        for (int o = 1; o < 32; o <<= 1) {
            int u = __shfl_up_sync(0xffffffffu, v, o);
            if (lane >= o) v += u;
        }
        wcnt[lane] = v;
    }
    __syncthreads();
    if (tid == 0) {
        int tot = wcnt[31];
        d_fgcnt[b] = tot < SP ? tot : SP;
    }
    int pos = wcnt[wid] - cnt;
#pragma unroll
    for (int k = 0; k < 9; k++) {
        int loc = k * 32 + lane;
        int a = base + loc;
        bool p = (loc < CH) && (a < AA) && (d_inin[b * AA + a] != 0ull);
        unsigned bal = __ballot_sync(0xffffffffu, p);
        int my = __popc(bal & ((1u << lane) - 1u));
        if (p && pos + my < SP) {
            d_fgidx[b * SP + pos + my] = a;
            d_inv  [b * AA + a]        = pos + my;
        }
        pos += __popc(bal);
    }
}

// ---------------- kernel 3: candidate prep + suml (16 lanes / candidate) -----
__global__ void __launch_bounds__(128) k_prep(const float* __restrict__ outp) {
    int b   = blockIdx.y;
    int cnt = d_fgcnt[b];
    if (blockIdx.x * 8 >= cnt) return;
    int tid  = threadIdx.x;
    int lane = tid & 31, warp = tid >> 5;
    int grp  = lane >> 4, sub = lane & 15;
    int i    = blockIdx.x * 8 + warp * 2 + grp;
    bool valid = (i < cnt);
    int ic = valid ? i : (cnt - 1);
    int a  = d_fgidx[b * SP + ic];
    const float* o = outp + (size_t)(b * AA + a) * ROW;
    float obj = o[4];
    float prod = 1.0f;
#pragma unroll
    for (int c = 0; c < 5; c++) {
        float x = o[5 + sub * 5 + c] * obj;
        prod *= (1.0f - x * rsqrtf(x));
    }
    float l = __logf(prod);
    l += __shfl_xor_sync(0xffffffffu, l, 1);
    l += __shfl_xor_sync(0xffffffffu, l, 2);
    l += __shfl_xor_sync(0xffffffffu, l, 4);
    l += __shfl_xor_sync(0xffffffffu, l, 8);
    if (sub == 0 && valid) {
        float bx = o[0], by = o[1], bw = o[2], bh = o[3];
        int idx = b * SP + i;
        d_cbox [idx] = make_float4(bx - bw * 0.5f, by - bh * 0.5f,
                                   bx + bw * 0.5f, by + bh * 0.5f);
        d_cmeta[idx] = make_float4(bw * bh, obj, l, 0.0f);
        d_cinin[idx] = d_inin[b * AA + a];
    }
}

// ---------------- kernel 4: fused pairwise cost/iou + dynamic_k + top-k ------
// Block per (b,g), 256 threads x 6 candidates. IoU and cost computed in
// registers (identical formulas to the old k_pair); cost also stored to
// d_cost for k_fgloss's multi-match argmin. d_iou never materialized.
__global__ void __launch_bounds__(256) k_pairsel(const float* __restrict__ outp,
                                                 const float* __restrict__ labels) {
    __shared__ unsigned long long swp[8];
    __shared__ unsigned long long sbest;
    int bg = blockIdx.x;
    int b  = bg / GG;
    int g  = bg - b * GG;
    int tid = threadIdx.x, lane = tid & 31, wid = tid >> 5;
    int N = d_fgcnt[b];

    const float* L = labels + (b * GG + g) * 5;   // uniform broadcast loads
    int   gc  = (int)L[0];
    float gxv = L[1], gyv = L[2], gwv = L[3], ghv = L[4];
    float qx1 = gxv - gwv * 0.5f, qx2 = gxv + gwv * 0.5f;
    float qy1 = gyv - ghv * 0.5f, qy2 = gyv + ghv * 0.5f;
    float qar = gwv * ghv;

    unsigned kiou[6], kcst[6];
#pragma unroll
    for (int j = 0; j < 6; j++) {
        int i = tid + j * 256;
        if (i < N) {
            int idx = b * SP + i;
            float4 box  = d_cbox [idx];
            float4 meta = d_cmeta[idx];
            unsigned long long inin = d_cinin[idx];
            float w = fminf(box.z, qx2) - fmaxf(box.x, qx1);
            float h = fminf(box.w, qy2) - fmaxf(box.y, qy1);
            float inter = fmaxf(w, 0.0f) * fmaxf(h, 0.0f);
            float den = meta.x + qar - inter;
            float y = __uint_as_float(0x7EF311C3u - __float_as_uint(den));
            y = y * (2.0f - den * y);
            y = y * (2.0f - den * y);
            float iou = inter * y;
            kiou[j] = __float_as_uint(iou);
            float cost = FLT_MAX;
            if ((inin >> g) & 1ull) {
                int a = d_fgidx[b * SP + i];
                float xg = outp[(size_t)(b * AA + a) * ROW + 5 + gc] * meta.y;
                float pg = xg * rsqrtf(xg);
                cost = -meta.z - (0.5f * __logf(xg) - __logf(1.0f - pg))
                       - 3.0f * __logf(iou + 1e-8f);
            }
            d_cost[(size_t)bg * SP + i] = cost;
            unsigned cb = __float_as_uint(cost);
            kcst[j] = (cb & 0x80000000u) ? ~cb : (cb | 0x80000000u);
        } else {
            kiou[j] = 0u;
            kcst[j] = 0xFFFFFFFFu;   // +inf order-mapped
        }
    }

    // phase A: sum of top-10 iou values
    float sum = 0.0f;
    unsigned long long prev = ~0ull;
    for (int t = 0; t < 10; t++) {
        unsigned long long best = 0ull;
#pragma unroll
        for (int j = 0; j < 6; j++) {
            unsigned long long key =
                ((unsigned long long)kiou[j] << 32) | (unsigned)(tid + j * 256);
            if (key < prev && key > best) best = key;
        }
#pragma unroll
        for (int o = 16; o > 0; o >>= 1) {
            unsigned long long oth = __shfl_xor_sync(0xffffffffu, best, o);
            if (oth > best) best = oth;
        }
        if (lane == 0) swp[wid] = best;
        __syncthreads();
        if (tid == 0) {
            unsigned long long m = swp[0];
#pragma unroll
            for (int w2 = 1; w2 < 8; w2++) if (swp[w2] > m) m = swp[w2];
            sbest = m;
        }
        __syncthreads();
        prev = sbest;
        sum += __uint_as_float((unsigned)(prev >> 32));
    }
    int k = (int)sum;
    if (k < 1)  k = 1;
    if (k > 10) k = 10;

    // phase B: k smallest (cost, idx) — stable argsort tie-break by index
    prev = 0ull;
    for (int t = 0; t < k; t++) {
        unsigned long long best = ~0ull;
#pragma unroll
        for (int j = 0; j < 6; j++) {
            unsigned long long key =
                ((unsigned long long)kcst[j] << 32) | (unsigned)(tid + j * 256);
            if (key > prev && key < best) best = key;
        }
#pragma unroll
        for (int o = 16; o > 0; o >>= 1) {
            unsigned long long oth = __shfl_xor_sync(0xffffffffu, best, o);
            if (oth < best) best = oth;
        }
        if (lane == 0) swp[wid] = best;
        __syncthreads();
        if (tid == 0) {
            unsigned long long m = swp[0];
#pragma unroll
            for (int w2 = 1; w2 < 8; w2++) if (swp[w2] < m) m = swp[w2];
            sbest = m;
            int i = (int)(unsigned)(m & 0xFFFFFFFFull);
            if (m != ~0ull && i < N) {
                int a = d_fgidx[b * SP + i];
                unsigned long long old =
                    atomicOr(&d_match[b * AA + a], 1ull << g);
                if (old == 0ull) {            // first match -> compact
                    int pos = atomicAdd(&d_mcnt[b], 1);
                    if (pos < MM) d_midx[b * MM + pos] = a;
                }
            }
        }
        __syncthreads();
        prev = sbest;
    }
}

// ---------------- kernel 5: heavy losses on matched anchors only -------------
__global__ void __launch_bounds__(128) k_fgloss(const float* __restrict__ outp,
                                                const float* __restrict__ orig,
                                                const float* __restrict__ labels,
                                                const float* __restrict__ xsA,
                                                const float* __restrict__ ysA,
                                                const float* __restrict__ stA) {
    __shared__ float s[8];
    int b = blockIdx.y;
    int j = blockIdx.x * 128 + threadIdx.x;
    float v_iou = 0.0f, v_cls = 0.0f, v_l1 = 0.0f, v_obj = 0.0f;
    int mc2 = d_mcnt[b]; if (mc2 > MM) mc2 = MM;
    if (j < mc2) {
        int a = d_midx[b * MM + j];
        unsigned long long m = d_match[b * AA + a];
        int i = d_inv[b * AA + a];
        int mg;
        if (__popcll(m) > 1) {
            float best = FLT_MAX; mg = 0;
            for (int g = 0; g < GG; g++) {
                float c = d_cost[(size_t)(b * GG + g) * SP + i];
                if (c < best) { best = c; mg = g; }
            }
        } else {
            mg = __ffsll((long long)m) - 1;
        }
        const float* L = labels + (b * GG + mg) * 5;
        int   mc = (int)L[0];
        float gxv = L[1], gyv = L[2], gwv = L[3], ghv = L[4];

        const float* o = outp + (size_t)(b * AA + a) * ROW;
        v_obj = -o[4];                       // fg-dependent obj BCE term
        float bx = o[0], by = o[1], bw = o[2], bh = o[3];
        float tlx = fmaxf(bx - bw * 0.5f, gxv - gwv * 0.5f);
        float tly = fmaxf(by - bh * 0.5f, gyv - ghv * 0.5f);
        float brx = fminf(bx + bw * 0.5f, gxv + gwv * 0.5f);
        float bry = fminf(by + bh * 0.5f, gyv + ghv * 0.5f);
        float inter = (tlx < brx && tly < bry) ? (brx - tlx) * (bry - tly) : 0.0f;
        float pred_iou = inter / (bw * bh + gwv * ghv - inter);
        float iou      = inter / (bw * bh + gwv * ghv - inter + 1e-16f);
        v_iou = 1.0f - iou * iou;

        float cl = 0.0f;
#pragma unroll 8
        for (int c = 0; c < CC; c++) {
            float xl = o[5 + c];
            float t  = (c == mc) ? pred_iou : 0.0f;
            cl += fmaxf(xl, 0.0f) - xl * t + log1pf(expf(-fabsf(xl)));
        }
        v_cls = cl;

        float st = stA[a];
        float t0 = gxv / st - xsA[a];
        float t1 = gyv / st - ysA[a];
        float t2 = logf(gwv / st + 1e-8f);
        float t3 = logf(ghv / st + 1e-8f);
        const float* op = orig + (size_t)(b * AA + a) * 4;
        v_l1 = fabsf(op[0] - t0) + fabsf(op[1] - t1) +
               fabsf(op[2] - t2) + fabsf(op[3] - t3);
    }
    float r;
    r = blockSum(v_iou, s); if (threadIdx.x == 0) atomicAdd(&d_acc[0], (double)r);
    r = blockSum(v_obj, s); if (threadIdx.x == 0) atomicAdd(&d_acc[1], (double)r);
    r = blockSum(v_cls, s); if (threadIdx.x == 0) atomicAdd(&d_acc[2], (double)r);
    r = blockSum(v_l1,  s); if (threadIdx.x == 0) atomicAdd(&d_acc[3], (double)r);
}

// ---------------- kernel 6: finalize + reset accumulators for next replay ----
__global__ void k_final(float* out) {
    int tid = threadIdx.x;
    if (tid == 0) {
        int tot = 0;
        for (int b2 = 0; b2 < BB; b2++) tot += d_mcnt[b2];
        double nfg = (double)tot;
        if (nfg < 1.0) nfg = 1.0;
        float liou = (float)(5.0 * d_acc[0] / nfg);
        float lobj = (float)(d_acc[1] / nfg);
        float lcls = (float)(d_acc[2] / nfg);
        float ll1  = (float)(d_acc[3] / nfg);
        out[0] = liou + lobj + lcls + ll1;
        out[1] = liou;
        out[2] = lobj;
        out[3] = lcls;
        out[4] = ll1;
        out[5] = (float)(nfg / (double)(BB * GG));
    }
    __syncthreads();
    d_mcnt[tid] = 0;
    if (tid < 6) d_acc[tid] = 0.0;
}

// ---------------- launch ----------------
extern "C" void kernel_launch(void* const* d_in, const int* in_sizes, int n_in,
                              void* d_out, int out_size) {
    const float* outputs = (const float*)d_in[0];
    const float* origin  = (const float*)d_in[1];
    const float* labels  = (const float*)d_in[2];
    const float* xs      = (const float*)d_in[3];
    const float* ys      = (const float*)d_in[4];
    const float* st      = (const float*)d_in[5];

    k_isin<<<dim3((AA + 255) / 256, BB), 256>>>(labels, outputs);
    k_scan<<<BB, 1024>>>();
    k_prep<<<dim3(SP / 8, BB), 128>>>(outputs);
    k_pairsel<<<BB * GG, 256>>>(outputs, labels);
    k_fgloss<<<dim3(MM / 128, BB), 128>>>(outputs, origin, labels, xs, ys, st);
    k_final<<<1, 32>>>((float*)d_out);
}

// round 10
// speedup vs baseline: 1.6027x; 1.1063x over previous
#include <cuda_runtime.h>
#include <math.h>
#include <float.h>

#define BB 32
#define AA 8400
#define GG 40
#define CC 80
#define ROW 85
#define SP 1536      // max candidates per batch; true bound ~1080
#define MM 512       // max matched anchors per batch
#define SL 256       // in-region pairs per (b,g) cap (true bound ~48)

// ---------------- scratch (device globals; zero-init at load) ----------------
__device__ unsigned long long d_match[BB * AA];
__device__ unsigned long long d_inin [BB * AA];
__device__ unsigned long long d_cinin[BB * SP];
__device__ int    d_fgidx[BB * SP];
__device__ int    d_inv  [BB * AA];
__device__ int    d_fgcnt[BB];
__device__ int    d_mcnt [BB];     // zeroed by k_final each run
__device__ int    d_midx [BB * MM];
__device__ double d_acc[6];        // zeroed by k_final each run
__device__ float4 d_cbox [BB * SP];   // x1,y1,x2,y2
__device__ float4 d_cmeta[BB * SP];   // area, obj, suml, -

// ---------------- block reduction helper ----------------
__device__ __forceinline__ float blockSum(float v, float* s) {
    int tid = threadIdx.x;
#pragma unroll
    for (int o = 16; o > 0; o >>= 1) v += __shfl_xor_sync(0xffffffffu, v, o);
    if ((tid & 31) == 0) s[tid >> 5] = v;
    __syncthreads();
    float r = 0.0f;
    if (tid < (blockDim.x >> 5)) r = s[tid];
#pragma unroll
    for (int o = 4; o > 0; o >>= 1) r += __shfl_xor_sync(0xffffffffu, r, o);
    __syncthreads();
    return r;   // valid in thread 0
}

// ---------------- kernel 1: analytic mask + fg-independent obj BCE ----------
__global__ void k_isin(const float* __restrict__ labels,
                       const float* __restrict__ outp) {
    __shared__ float sgx[GG], sgy[GG];
    __shared__ float s[8];
    int b = blockIdx.y;
    int tid = threadIdx.x;
    if (tid < GG) {
        sgx[tid] = labels[(b * GG + tid) * 5 + 1];
        sgy[tid] = labels[(b * GG + tid) * 5 + 2];
    }
    __syncthreads();
    int a = blockIdx.x * blockDim.x + tid;
    float vo = 0.0f;
    if (a < AA) {
        float sc; int n, rel;
        if (a < 6400)      { sc = 8.0f;  n = 80; rel = a;        }
        else if (a < 8000) { sc = 16.0f; n = 40; rel = a - 6400; }
        else               { sc = 32.0f; n = 20; rel = a - 8000; }
        float xc = ((float)(rel % n) + 0.5f) * sc;
        float yc = ((float)(rel / n) + 0.5f) * sc;
        float r  = 1.5f * sc;
        unsigned long long m = 0ull;
#pragma unroll 8
        for (int g = 0; g < GG; g++) {
            bool in = (xc > sgx[g] - r) && (xc < sgx[g] + r) &&
                      (yc > sgy[g] - r) && (yc < sgy[g] + r);
            if (in) m |= (1ull << g);
        }
        d_inin [b * AA + a] = m;
        d_match[b * AA + a] = 0ull;
        float x = outp[(size_t)(b * AA + a) * ROW + 4];
        vo = fmaxf(x, 0.0f) + __logf(1.0f + __expf(-fabsf(x)));
    }
    float r = blockSum(vo, s);
    if (tid == 0) atomicAdd(&d_acc[1], (double)r);
}

// ---------------- kernel 2: ordered compaction (wide warp-ballot scan) -------
__global__ void __launch_bounds__(1024) k_scan() {
    __shared__ int wcnt[32];
    int b = blockIdx.x;
    int tid = threadIdx.x, wid = tid >> 5, lane = tid & 31;
    const int CH = 263;
    int base = wid * CH;
    int cnt = 0;
#pragma unroll
    for (int k = 0; k < 9; k++) {
        int loc = k * 32 + lane;
        int a = base + loc;
        bool p = (loc < CH) && (a < AA) && (d_inin[b * AA + a] != 0ull);
        cnt += __popc(__ballot_sync(0xffffffffu, p));
    }
    if (lane == 0) wcnt[wid] = cnt;
    __syncthreads();
    if (wid == 0) {
        int v = wcnt[lane];
#pragma unroll
        for (int o = 1; o < 32; o <<= 1) {
            int u = __shfl_up_sync(0xffffffffu, v, o);
            if (lane >= o) v += u;
        }
        wcnt[lane] = v;
    }
    __syncthreads();
    if (tid == 0) {
        int tot = wcnt[31];
        d_fgcnt[b] = tot < SP ? tot : SP;
    }
    int pos = wcnt[wid] - cnt;
#pragma unroll
    for (int k = 0; k < 9; k++) {
        int loc = k * 32 + lane;
        int a = base + loc;
        bool p = (loc < CH) && (a < AA) && (d_inin[b * AA + a] != 0ull);
        unsigned bal = __ballot_sync(0xffffffffu, p);
        int my = __popc(bal & ((1u << lane) - 1u));
        if (p && pos + my < SP) {
            d_fgidx[b * SP + pos + my] = a;
            d_inv  [b * AA + a]        = pos + my;
        }
        pos += __popc(bal);
    }
}

// ---------------- kernel 3: candidate prep + suml (16 lanes / candidate) -----
__global__ void __launch_bounds__(128) k_prep(const float* __restrict__ outp) {
    int b   = blockIdx.y;
    int cnt = d_fgcnt[b];
    if (blockIdx.x * 8 >= cnt) return;
    int tid  = threadIdx.x;
    int lane = tid & 31, warp = tid >> 5;
    int grp  = lane >> 4, sub = lane & 15;
    int i    = blockIdx.x * 8 + warp * 2 + grp;
    bool valid = (i < cnt);
    int ic = valid ? i : (cnt - 1);
    int a  = d_fgidx[b * SP + ic];
    const float* o = outp + (size_t)(b * AA + a) * ROW;
    float obj = o[4];
    float prod = 1.0f;
#pragma unroll
    for (int c = 0; c < 5; c++) {
        float x = o[5 + sub * 5 + c] * obj;
        prod *= (1.0f - x * rsqrtf(x));
    }
    float l = __logf(prod);
    l += __shfl_xor_sync(0xffffffffu, l, 1);
    l += __shfl_xor_sync(0xffffffffu, l, 2);
    l += __shfl_xor_sync(0xffffffffu, l, 4);
    l += __shfl_xor_sync(0xffffffffu, l, 8);
    if (sub == 0 && valid) {
        float bx = o[0], by = o[1], bw = o[2], bh = o[3];
        int idx = b * SP + i;
        d_cbox [idx] = make_float4(bx - bw * 0.5f, by - bh * 0.5f,
                                   bx + bw * 0.5f, by + bh * 0.5f);
        d_cmeta[idx] = make_float4(bw * bh, obj, l, 0.0f);
        d_cinin[idx] = d_inin[b * AA + a];
    }
}

// ---------------- kernel 4: fused pair cost + dynamic_k + top-k select ------
// Block per (b,g), 256 threads x 6 candidates.
// Phase A: warp-local removal-based top-10 iou (32-bit), warp0 merge.
// Phase B: in-region cost keys compacted to smem, warp0 k-pass selection.
__global__ void __launch_bounds__(256) k_pairsel(const float* __restrict__ outp,
                                                 const float* __restrict__ labels) {
    __shared__ unsigned swtop[8 * 10];           // per-warp top-10 iou bits
    __shared__ unsigned long long slist[SL];     // in-region cost keys
    __shared__ int scnt;
    int bg = blockIdx.x;
    int b  = bg / GG;
    int g  = bg - b * GG;
    int tid = threadIdx.x, lane = tid & 31, wid = tid >> 5;
    int N = d_fgcnt[b];
    if (tid == 0) scnt = 0;

    const float* L = labels + (b * GG + g) * 5;   // uniform broadcast loads
    int   gc  = (int)L[0];
    float gxv = L[1], gyv = L[2], gwv = L[3], ghv = L[4];
    float qx1 = gxv - gwv * 0.5f, qx2 = gxv + gwv * 0.5f;
    float qy1 = gyv - ghv * 0.5f, qy2 = gyv + ghv * 0.5f;
    float qar = gwv * ghv;
    __syncthreads();                              // scnt visible

    unsigned viou[6];
#pragma unroll
    for (int j = 0; j < 6; j++) {
        int i = tid + j * 256;
        viou[j] = 0u;
        if (i < N) {
            int idx = b * SP + i;
            float4 box  = d_cbox [idx];
            float4 meta = d_cmeta[idx];
            unsigned long long inin = d_cinin[idx];
            float w = fminf(box.z, qx2) - fmaxf(box.x, qx1);
            float h = fminf(box.w, qy2) - fmaxf(box.y, qy1);
            float inter = fmaxf(w, 0.0f) * fmaxf(h, 0.0f);
            float den = meta.x + qar - inter;
            float y = __uint_as_float(0x7EF311C3u - __float_as_uint(den));
            y = y * (2.0f - den * y);
            y = y * (2.0f - den * y);
            float iou = inter * y;
            viou[j] = __float_as_uint(iou);
            if ((inin >> g) & 1ull) {
                int a = d_fgidx[b * SP + i];
                float xg = outp[(size_t)(b * AA + a) * ROW + 5 + gc] * meta.y;
                float pg = xg * rsqrtf(xg);
                float cost = -meta.z - (0.5f * __logf(xg) - __logf(1.0f - pg))
                             - 3.0f * __logf(iou + 1e-8f);
                unsigned cb = __float_as_uint(cost);
                cb = (cb & 0x80000000u) ? ~cb : (cb | 0x80000000u);
                int pos = atomicAdd(&scnt, 1);
                if (pos < SL)
                    slist[pos] = ((unsigned long long)cb << 32) | (unsigned)i;
            }
        }
    }

    // phase A (warp-local): removal-based top-10 of this warp's 192 ious
    for (int t = 0; t < 10; t++) {
        unsigned best = 0u; int bj = 0;
#pragma unroll
        for (int j = 0; j < 6; j++)
            if (viou[j] > best) { best = viou[j]; bj = j; }
        unsigned wmax = best;
#pragma unroll
        for (int o = 16; o > 0; o >>= 1) {
            unsigned oth = __shfl_xor_sync(0xffffffffu, wmax, o);
            if (oth > wmax) wmax = oth;
        }
        unsigned ball = __ballot_sync(0xffffffffu, best == wmax);
        if (lane == (__ffs(ball) - 1)) viou[bj] = 0u;   // remove one instance
        if (lane == 0) swtop[wid * 10 + t] = wmax;
    }
    __syncthreads();

    if (wid != 0) return;
    // warp 0: merge 80 values, sum top-10 in descending order
    unsigned mv[3];
    mv[0] = swtop[lane];
    mv[1] = swtop[lane + 32];
    mv[2] = (lane + 64 < 80) ? swtop[lane + 64] : 0u;
    float sum = 0.0f;
    for (int t = 0; t < 10; t++) {
        unsigned best = 0u; int bj = 0;
#pragma unroll
        for (int j = 0; j < 3; j++)
            if (mv[j] > best) { best = mv[j]; bj = j; }
        unsigned wmax = best;
#pragma unroll
        for (int o = 16; o > 0; o >>= 1) {
            unsigned oth = __shfl_xor_sync(0xffffffffu, wmax, o);
            if (oth > wmax) wmax = oth;
        }
        unsigned ball = __ballot_sync(0xffffffffu, best == wmax);
        if (lane == (__ffs(ball) - 1)) mv[bj] = 0u;
        sum += __uint_as_float(wmax);
    }
    int k = (int)sum;
    if (k < 1)  k = 1;
    if (k > 10) k = 10;

    // phase B (warp 0): k smallest cost keys from the compacted list
    int M = scnt; if (M > SL) M = SL;
    unsigned long long kk[8];
#pragma unroll
    for (int j = 0; j < 8; j++) {
        int p = lane + j * 32;
        kk[j] = (p < M) ? slist[p] : ~0ull;
    }
    for (int t = 0; t < k; t++) {
        unsigned long long lbest = ~0ull; int bj = 0;
#pragma unroll
        for (int j = 0; j < 8; j++)
            if (kk[j] < lbest) { lbest = kk[j]; bj = j; }
        unsigned long long wmin = lbest;
#pragma unroll
        for (int o = 16; o > 0; o >>= 1) {
            unsigned long long oth = __shfl_xor_sync(0xffffffffu, wmin, o);
            if (oth < wmin) wmin = oth;
        }
        if (wmin == ~0ull) break;
        unsigned ball = __ballot_sync(0xffffffffu, lbest == wmin);
        if (lane == (__ffs(ball) - 1)) kk[bj] = ~0ull;  // remove (keys unique)
        if (lane == 0) {
            int i = (int)(unsigned)(wmin & 0xFFFFFFFFull);
            int a = d_fgidx[b * SP + i];
            unsigned long long old = atomicOr(&d_match[b * AA + a], 1ull << g);
            if (old == 0ull) {                 // first match -> compact
                int pos = atomicAdd(&d_mcnt[b], 1);
                if (pos < MM) d_midx[b * MM + pos] = a;
            }
        }
    }
}

// ---------------- kernel 5: heavy losses on matched anchors only -------------
__global__ void __launch_bounds__(128) k_fgloss(const float* __restrict__ outp,
                                                const float* __restrict__ orig,
                                                const float* __restrict__ labels,
                                                const float* __restrict__ xsA,
                                                const float* __restrict__ ysA,
                                                const float* __restrict__ stA) {
    __shared__ float s[8];
    int b = blockIdx.y;
    int j = blockIdx.x * 128 + threadIdx.x;
    float v_iou = 0.0f, v_cls = 0.0f, v_l1 = 0.0f, v_obj = 0.0f;
    int mc2 = d_mcnt[b]; if (mc2 > MM) mc2 = MM;
    if (j < mc2) {
        int a = d_midx[b * MM + j];
        unsigned long long m = d_match[b * AA + a];
        int i = d_inv[b * AA + a];
        int idx = b * SP + i;
        int mg;
        if (__popcll(m) > 1) {
            // best_gt = argmin cost over in-region g's (recomputed exactly as
            // in k_pairsel; out-of-region +1e6 costs can never win)
            float4 box  = d_cbox [idx];
            float4 meta = d_cmeta[idx];
            unsigned long long mm = d_cinin[idx];
            const float* orow = outp + (size_t)(b * AA + a) * ROW;
            float best = FLT_MAX; mg = 0;
            while (mm) {
                int g = __ffsll((long long)mm) - 1;
                mm &= mm - 1;
                const float* L = labels + (b * GG + g) * 5;
                int   gc  = (int)L[0];
                float gxv = L[1], gyv = L[2], gwv = L[3], ghv = L[4];
                float qx1 = gxv - gwv * 0.5f, qx2 = gxv + gwv * 0.5f;
                float qy1 = gyv - ghv * 0.5f, qy2 = gyv + ghv * 0.5f;
                float qar = gwv * ghv;
                float w = fminf(box.z, qx2) - fmaxf(box.x, qx1);
                float h = fminf(box.w, qy2) - fmaxf(box.y, qy1);
                float inter = fmaxf(w, 0.0f) * fmaxf(h, 0.0f);
                float den = meta.x + qar - inter;
                float y = __uint_as_float(0x7EF311C3u - __float_as_uint(den));
                y = y * (2.0f - den * y);
                y = y * (2.0f - den * y);
                float iou = inter * y;
                float xg = orow[5 + gc] * meta.y;
                float pg = xg * rsqrtf(xg);
                float c = -meta.z - (0.5f * __logf(xg) - __logf(1.0f - pg))
                          - 3.0f * __logf(iou + 1e-8f);
                if (c < best) { best = c; mg = g; }
            }
        } else {
            mg = __ffsll((long long)m) - 1;
        }
        const float* L = labels + (b * GG + mg) * 5;
        int   mc = (int)L[0];
        float gxv = L[1], gyv = L[2], gwv = L[3], ghv = L[4];

        const float* o = outp + (size_t)(b * AA + a) * ROW;
        v_obj = -o[4];                       // fg-dependent obj BCE term
        float bx = o[0], by = o[1], bw = o[2], bh = o[3];
        float tlx = fmaxf(bx - bw * 0.5f, gxv - gwv * 0.5f);
        float tly = fmaxf(by - bh * 0.5f, gyv - ghv * 0.5f);
        float brx = fminf(bx + bw * 0.5f, gxv + gwv * 0.5f);
        float bry = fminf(by + bh * 0.5f, gyv + ghv * 0.5f);
        float inter = (tlx < brx && tly < bry) ? (brx - tlx) * (bry - tly) : 0.0f;
        float pred_iou = inter / (bw * bh + gwv * ghv - inter);
        float iou      = inter / (bw * bh + gwv * ghv - inter + 1e-16f);
        v_iou = 1.0f - iou * iou;

        float cl = 0.0f;
#pragma unroll 8
        for (int c = 0; c < CC; c++) {
            float xl = o[5 + c];
            float t  = (c == mc) ? pred_iou : 0.0f;
            cl += fmaxf(xl, 0.0f) - xl * t + log1pf(expf(-fabsf(xl)));
        }
        v_cls = cl;

        float st = stA[a];
        float t0 = gxv / st - xsA[a];
        float t1 = gyv / st - ysA[a];
        float t2 = logf(gwv / st + 1e-8f);
        float t3 = logf(ghv / st + 1e-8f);
        const float* op = orig + (size_t)(b * AA + a) * 4;
        v_l1 = fabsf(op[0] - t0) + fabsf(op[1] - t1) +
               fabsf(op[2] - t2) + fabsf(op[3] - t3);
    }
    float r;
    r = blockSum(v_iou, s); if (threadIdx.x == 0) atomicAdd(&d_acc[0], (double)r);
    r = blockSum(v_obj, s); if (threadIdx.x == 0) atomicAdd(&d_acc[1], (double)r);
    r = blockSum(v_cls, s); if (threadIdx.x == 0) atomicAdd(&d_acc[2], (double)r);
    r = blockSum(v_l1,  s); if (threadIdx.x == 0) atomicAdd(&d_acc[3], (double)r);
}

// ---------------- kernel 6: finalize + reset accumulators for next replay ----
__global__ void k_final(float* out) {
    int tid = threadIdx.x;
    if (tid == 0) {
        int tot = 0;
        for (int b2 = 0; b2 < BB; b2++) tot += d_mcnt[b2];
        double nfg = (double)tot;
        if (nfg < 1.0) nfg = 1.0;
        float liou = (float)(5.0 * d_acc[0] / nfg);
        float lobj = (float)(d_acc[1] / nfg);
        float lcls = (float)(d_acc[2] / nfg);
        float ll1  = (float)(d_acc[3] / nfg);
        out[0] = liou + lobj + lcls + ll1;
        out[1] = liou;
        out[2] = lobj;
        out[3] = lcls;
        out[4] = ll1;
        out[5] = (float)(nfg / (double)(BB * GG));
    }
    __syncthreads();
    d_mcnt[tid] = 0;
    if (tid < 6) d_acc[tid] = 0.0;
}

// ---------------- launch ----------------
extern "C" void kernel_launch(void* const* d_in, const int* in_sizes, int n_in,
                              void* d_out, int out_size) {
    const float* outputs = (const float*)d_in[0];
    const float* origin  = (const float*)d_in[1];
    const float* labels  = (const float*)d_in[2];
    const float* xs      = (const float*)d_in[3];
    const float* ys      = (const float*)d_in[4];
    const float* st      = (const float*)d_in[5];

    k_isin<<<dim3((AA + 255) / 256, BB), 256>>>(labels, outputs);
    k_scan<<<BB, 1024>>>();
    k_prep<<<dim3(SP / 8, BB), 128>>>(outputs);
    k_pairsel<<<BB * GG, 256>>>(outputs, labels);
    k_fgloss<<<dim3(MM / 128, BB), 128>>>(outputs, origin, labels, xs, ys, st);
    k_final<<<1, 32>>>((float*)d_out);
}

// round 11
// speedup vs baseline: 1.6530x; 1.0314x over previous
#include <cuda_runtime.h>
#include <math.h>
#include <float.h>

#define BB 32
#define AA 8400
#define GG 40
#define CC 80
#define ROW 85
#define SP 1536      // max candidates per batch; true bound ~1080
#define MM 512       // max matched anchors per batch
#define SL 64        // in-region pairs per (b,g) cap (geometric bound 27)

// ---------------- scratch (device globals; zero-init at load) ----------------
__device__ unsigned long long d_match[BB * AA];
__device__ unsigned long long d_inin [BB * AA];
__device__ unsigned long long d_cinin[BB * SP];
__device__ int    d_fgidx[BB * SP];
__device__ int    d_inv  [BB * AA];
__device__ int    d_fgcnt[BB];
__device__ int    d_mcnt [BB];     // zeroed by k_final each run
__device__ int    d_midx [BB * MM];
__device__ double d_acc[6];        // zeroed by k_final each run
__device__ float4 d_cbox [BB * SP];   // x1,y1,x2,y2
__device__ float4 d_cmeta[BB * SP];   // area, obj, suml, -

// ---------------- block reduction helper ----------------
__device__ __forceinline__ float blockSum(float v, float* s) {
    int tid = threadIdx.x;
#pragma unroll
    for (int o = 16; o > 0; o >>= 1) v += __shfl_xor_sync(0xffffffffu, v, o);
    if ((tid & 31) == 0) s[tid >> 5] = v;
    __syncthreads();
    float r = 0.0f;
    if (tid < (blockDim.x >> 5)) r = s[tid];
#pragma unroll
    for (int o = 4; o > 0; o >>= 1) r += __shfl_xor_sync(0xffffffffu, r, o);
    __syncthreads();
    return r;   // valid in thread 0
}

// ---------------- kernel 1: analytic mask + fg-independent obj BCE ----------
__global__ void k_isin(const float* __restrict__ labels,
                       const float* __restrict__ outp) {
    __shared__ float sgx[GG], sgy[GG];
    __shared__ float s[8];
    int b = blockIdx.y;
    int tid = threadIdx.x;
    if (tid < GG) {
        sgx[tid] = labels[(b * GG + tid) * 5 + 1];
        sgy[tid] = labels[(b * GG + tid) * 5 + 2];
    }
    __syncthreads();
    int a = blockIdx.x * blockDim.x + tid;
    float vo = 0.0f;
    if (a < AA) {
        float sc; int n, rel;
        if (a < 6400)      { sc = 8.0f;  n = 80; rel = a;        }
        else if (a < 8000) { sc = 16.0f; n = 40; rel = a - 6400; }
        else               { sc = 32.0f; n = 20; rel = a - 8000; }
        float xc = ((float)(rel % n) + 0.5f) * sc;
        float yc = ((float)(rel / n) + 0.5f) * sc;
        float r  = 1.5f * sc;
        unsigned long long m = 0ull;
#pragma unroll 8
        for (int g = 0; g < GG; g++) {
            bool in = (xc > sgx[g] - r) && (xc < sgx[g] + r) &&
                      (yc > sgy[g] - r) && (yc < sgy[g] + r);
            if (in) m |= (1ull << g);
        }
        d_inin [b * AA + a] = m;
        d_match[b * AA + a] = 0ull;
        float x = outp[(size_t)(b * AA + a) * ROW + 4];
        vo = fmaxf(x, 0.0f) + __logf(1.0f + __expf(-fabsf(x)));
    }
    float r = blockSum(vo, s);
    if (tid == 0) atomicAdd(&d_acc[1], (double)r);
}

// ---------------- kernel 2: ordered compaction (wide warp-ballot scan) -------
__global__ void __launch_bounds__(1024) k_scan() {
    __shared__ int wcnt[32];
    int b = blockIdx.x;
    int tid = threadIdx.x, wid = tid >> 5, lane = tid & 31;
    const int CH = 263;
    int base = wid * CH;
    int cnt = 0;
#pragma unroll
    for (int k = 0; k < 9; k++) {
        int loc = k * 32 + lane;
        int a = base + loc;
        bool p = (loc < CH) && (a < AA) && (d_inin[b * AA + a] != 0ull);
        cnt += __popc(__ballot_sync(0xffffffffu, p));
    }
    if (lane == 0) wcnt[wid] = cnt;
    __syncthreads();
    if (wid == 0) {
        int v = wcnt[lane];
#pragma unroll
        for (int o = 1; o < 32; o <<= 1) {
            int u = __shfl_up_sync(0xffffffffu, v, o);
            if (lane >= o) v += u;
        }
        wcnt[lane] = v;
    }
    __syncthreads();
    if (tid == 0) {
        int tot = wcnt[31];
        d_fgcnt[b] = tot < SP ? tot : SP;
    }
    int pos = wcnt[wid] - cnt;
#pragma unroll
    for (int k = 0; k < 9; k++) {
        int loc = k * 32 + lane;
        int a = base + loc;
        bool p = (loc < CH) && (a < AA) && (d_inin[b * AA + a] != 0ull);
        unsigned bal = __ballot_sync(0xffffffffu, p);
        int my = __popc(bal & ((1u << lane) - 1u));
        if (p && pos + my < SP) {
            d_fgidx[b * SP + pos + my] = a;
            d_inv  [b * AA + a]        = pos + my;
        }
        pos += __popc(bal);
    }
}

// ---------------- kernel 3: candidate prep + suml (16 lanes / candidate) -----
__global__ void __launch_bounds__(128) k_prep(const float* __restrict__ outp) {
    int b   = blockIdx.y;
    int cnt = d_fgcnt[b];
    if (blockIdx.x * 8 >= cnt) return;
    int tid  = threadIdx.x;
    int lane = tid & 31, warp = tid >> 5;
    int grp  = lane >> 4, sub = lane & 15;
    int i    = blockIdx.x * 8 + warp * 2 + grp;
    bool valid = (i < cnt);
    int ic = valid ? i : (cnt - 1);
    int a  = d_fgidx[b * SP + ic];
    const float* o = outp + (size_t)(b * AA + a) * ROW;
    float obj = o[4];
    float prod = 1.0f;
#pragma unroll
    for (int c = 0; c < 5; c++) {
        float x = o[5 + sub * 5 + c] * obj;
        prod *= (1.0f - x * rsqrtf(x));
    }
    float l = __logf(prod);
    l += __shfl_xor_sync(0xffffffffu, l, 1);
    l += __shfl_xor_sync(0xffffffffu, l, 2);
    l += __shfl_xor_sync(0xffffffffu, l, 4);
    l += __shfl_xor_sync(0xffffffffu, l, 8);
    if (sub == 0 && valid) {
        float bx = o[0], by = o[1], bw = o[2], bh = o[3];
        int idx = b * SP + i;
        d_cbox [idx] = make_float4(bx - bw * 0.5f, by - bh * 0.5f,
                                   bx + bw * 0.5f, by + bh * 0.5f);
        d_cmeta[idx] = make_float4(bw * bh, obj, l, 0.0f);
        d_cinin[idx] = d_inin[b * AA + a];
    }
}

// ---------------- kernel 4: fused pair iou + dynamic_k + top-k select -------
// Block per (b,g), 256 threads x 6 candidates.
// j-loop: pure-FMA iou + warp-aggregated append of in-region (iou,i).
// Phase A: cached-lane-max removal top-10 per warp, warp0 merge.
// Cost burst: parallel cost eval over the <=27-entry list.
// Phase B: warp0 k-pass stable selection.
__global__ void __launch_bounds__(256) k_pairsel(const float* __restrict__ outp,
                                                 const float* __restrict__ labels) {
    __shared__ unsigned swtop[8 * 10];
    __shared__ unsigned long long slist[SL];
    __shared__ int scnt;
    int bg = blockIdx.x;
    int b  = bg / GG;
    int g  = bg - b * GG;
    int tid = threadIdx.x, lane = tid & 31, wid = tid >> 5;
    int N = d_fgcnt[b];
    if (tid == 0) scnt = 0;

    const float* L = labels + (b * GG + g) * 5;   // uniform broadcast loads
    int   gc  = (int)L[0];
    float gxv = L[1], gyv = L[2], gwv = L[3], ghv = L[4];
    float qx1 = gxv - gwv * 0.5f, qx2 = gxv + gwv * 0.5f;
    float qy1 = gyv - ghv * 0.5f, qy2 = gyv + ghv * 0.5f;
    float qar = gwv * ghv;
    __syncthreads();                              // scnt visible

    float viou[6];
#pragma unroll
    for (int j = 0; j < 6; j++) {
        int i = tid + j * 256;
        float iou = 0.0f;
        bool inreg = false;
        if (i < N) {
            int idx = b * SP + i;
            float4 box  = d_cbox [idx];
            float4 meta = d_cmeta[idx];
            float w = fminf(box.z, qx2) - fmaxf(box.x, qx1);
            float h = fminf(box.w, qy2) - fmaxf(box.y, qy1);
            float inter = fmaxf(w, 0.0f) * fmaxf(h, 0.0f);
            float den = meta.x + qar - inter;
            float y = __uint_as_float(0x7EF311C3u - __float_as_uint(den));
            y = y * (2.0f - den * y);
            y = y * (2.0f - den * y);
            iou = inter * y;
            inreg = (d_cinin[idx] >> g) & 1ull;
        }
        viou[j] = iou;
        // warp-aggregated append of (iou, i)
        unsigned mb = __ballot_sync(0xffffffffu, inreg);
        if (mb) {
            int leader = __ffs(mb) - 1;
            int base = 0;
            if (lane == leader) base = atomicAdd(&scnt, __popc(mb));
            base = __shfl_sync(0xffffffffu, base, leader);
            if (inreg) {
                int p = base + __popc(mb & ((1u << lane) - 1u));
                if (p < SL)
                    slist[p] = ((unsigned long long)__float_as_uint(iou) << 32)
                               | (unsigned)i;
            }
        }
    }

    // phase A: cached-lane-max removal top-10 per warp
    float m = viou[0];
#pragma unroll
    for (int j = 1; j < 6; j++) m = fmaxf(m, viou[j]);
    for (int t = 0; t < 10; t++) {
        float wmax = m;
#pragma unroll
        for (int o = 16; o > 0; o >>= 1)
            wmax = fmaxf(wmax, __shfl_xor_sync(0xffffffffu, wmax, o));
        unsigned ball = __ballot_sync(0xffffffffu, m == wmax);
        if (lane == (__ffs(ball) - 1)) {
            bool cl = false;
#pragma unroll
            for (int j = 0; j < 6; j++)
                if (!cl && viou[j] == wmax) { viou[j] = 0.0f; cl = true; }
            m = viou[0];
#pragma unroll
            for (int j = 1; j < 6; j++) m = fmaxf(m, viou[j]);
        }
        if (lane == 0) swtop[wid * 10 + t] = __float_as_uint(wmax);
    }
    __syncthreads();                              // appends + swtop done

    // cost burst: parallel over the <=SL in-region entries
    int M = scnt; if (M > SL) M = SL;
    if (tid < M) {
        unsigned long long e = slist[tid];
        int i = (int)(unsigned)(e & 0xFFFFFFFFull);
        float iou = __uint_as_float((unsigned)(e >> 32));
        int idx = b * SP + i;
        float4 meta = d_cmeta[idx];
        int a = d_fgidx[idx];
        float xg = outp[(size_t)(b * AA + a) * ROW + 5 + gc] * meta.y;
        float pg = xg * rsqrtf(xg);
        float cost = -meta.z - (0.5f * __logf(xg) - __logf(1.0f - pg))
                     - 3.0f * __logf(iou + 1e-8f);
        unsigned cb = __float_as_uint(cost);
        cb = (cb & 0x80000000u) ? ~cb : (cb | 0x80000000u);
        slist[tid] = ((unsigned long long)cb << 32) | (unsigned)i;
    }
    __syncthreads();

    if (wid != 0) return;
    // warp0: merge 80 iou values, sum top-10 descending
    float mv[3];
    mv[0] = __uint_as_float(swtop[lane]);
    mv[1] = __uint_as_float(swtop[lane + 32]);
    mv[2] = (lane + 64 < 80) ? __uint_as_float(swtop[lane + 64]) : 0.0f;
    float mm = fmaxf(fmaxf(mv[0], mv[1]), mv[2]);
    float sum = 0.0f;
    for (int t = 0; t < 10; t++) {
        float wmax = mm;
#pragma unroll
        for (int o = 16; o > 0; o >>= 1)
            wmax = fmaxf(wmax, __shfl_xor_sync(0xffffffffu, wmax, o));
        unsigned ball = __ballot_sync(0xffffffffu, mm == wmax);
        if (lane == (__ffs(ball) - 1)) {
            bool cl = false;
#pragma unroll
            for (int j = 0; j < 3; j++)
                if (!cl && mv[j] == wmax) { mv[j] = 0.0f; cl = true; }
            mm = fmaxf(fmaxf(mv[0], mv[1]), mv[2]);
        }
        sum += wmax;
    }
    int k = (int)sum;
    if (k < 1)  k = 1;
    if (k > 10) k = 10;

    // phase B: k smallest (cost, idx) keys — stable tie-break by index
    unsigned long long kk[2];
#pragma unroll
    for (int j = 0; j < 2; j++) {
        int p = lane + j * 32;
        kk[j] = (p < M) ? slist[p] : ~0ull;
    }
    for (int t = 0; t < k; t++) {
        unsigned long long lbest = (kk[0] < kk[1]) ? kk[0] : kk[1];
        unsigned long long wmin = lbest;
#pragma unroll
        for (int o = 16; o > 0; o >>= 1) {
            unsigned long long oth = __shfl_xor_sync(0xffffffffu, wmin, o);
            if (oth < wmin) wmin = oth;
        }
        if (wmin == ~0ull) break;
        unsigned ball = __ballot_sync(0xffffffffu, lbest == wmin);
        if (lane == (__ffs(ball) - 1)) {          // keys unique: remove it
            if (kk[0] == wmin) kk[0] = ~0ull; else kk[1] = ~0ull;
        }
        if (lane == 0) {
            int i = (int)(unsigned)(wmin & 0xFFFFFFFFull);
            int a = d_fgidx[b * SP + i];
            unsigned long long old = atomicOr(&d_match[b * AA + a], 1ull << g);
            if (old == 0ull) {                    // first match -> compact
                int pos = atomicAdd(&d_mcnt[b], 1);
                if (pos < MM) d_midx[b * MM + pos] = a;
            }
        }
    }
}

// ---------------- kernel 5: heavy losses on matched anchors only -------------
__global__ void __launch_bounds__(128) k_fgloss(const float* __restrict__ outp,
                                                const float* __restrict__ orig,
                                                const float* __restrict__ labels,
                                                const float* __restrict__ xsA,
                                                const float* __restrict__ ysA,
                                                const float* __restrict__ stA) {
    __shared__ float s[8];
    int b = blockIdx.y;
    int j = blockIdx.x * 128 + threadIdx.x;
    float v_iou = 0.0f, v_cls = 0.0f, v_l1 = 0.0f, v_obj = 0.0f;
    int mc2 = d_mcnt[b]; if (mc2 > MM) mc2 = MM;
    if (j < mc2) {
        int a = d_midx[b * MM + j];
        unsigned long long m = d_match[b * AA + a];
        int i = d_inv[b * AA + a];
        int idx = b * SP + i;
        int mg;
        if (__popcll(m) > 1) {
            // best_gt = argmin cost over in-region g's (identical formulas to
            // k_pairsel; out-of-region +1e6 costs can never win)
            float4 box  = d_cbox [idx];
            float4 meta = d_cmeta[idx];
            unsigned long long mm = d_cinin[idx];
            const float* orow = outp + (size_t)(b * AA + a) * ROW;
            float best = FLT_MAX; mg = 0;
            while (mm) {
                int g = __ffsll((long long)mm) - 1;
                mm &= mm - 1;
                const float* L = labels + (b * GG + g) * 5;
                int   gc  = (int)L[0];
                float gxv = L[1], gyv = L[2], gwv = L[3], ghv = L[4];
                float qx1 = gxv - gwv * 0.5f, qx2 = gxv + gwv * 0.5f;
                float qy1 = gyv - ghv * 0.5f, qy2 = gyv + ghv * 0.5f;
                float qar = gwv * ghv;
                float w = fminf(box.z, qx2) - fmaxf(box.x, qx1);
                float h = fminf(box.w, qy2) - fmaxf(box.y, qy1);
                float inter = fmaxf(w, 0.0f) * fmaxf(h, 0.0f);
                float den = meta.x + qar - inter;
                float y = __uint_as_float(0x7EF311C3u - __float_as_uint(den));
                y = y * (2.0f - den * y);
                y = y * (2.0f - den * y);
                float iou = inter * y;
                float xg = orow[5 + gc] * meta.y;
                float pg = xg * rsqrtf(xg);
                float c = -meta.z - (0.5f * __logf(xg) - __logf(1.0f - pg))
                          - 3.0f * __logf(iou + 1e-8f);
                if (c < best) { best = c; mg = g; }
            }
        } else {
            mg = __ffsll((long long)m) - 1;
        }
        const float* L = labels + (b * GG + mg) * 5;
        int   mc = (int)L[0];
        float gxv = L[1], gyv = L[2], gwv = L[3], ghv = L[4];

        const float* o = outp + (size_t)(b * AA + a) * ROW;
        v_obj = -o[4];                       // fg-dependent obj BCE term
        float bx = o[0], by = o[1], bw = o[2], bh = o[3];
        float tlx = fmaxf(bx - bw * 0.5f, gxv - gwv * 0.5f);
        float tly = fmaxf(by - bh * 0.5f, gyv - ghv * 0.5f);
        float brx = fminf(bx + bw * 0.5f, gxv + gwv * 0.5f);
        float bry = fminf(by + bh * 0.5f, gyv + ghv * 0.5f);
        float inter = (tlx < brx && tly < bry) ? (brx - tlx) * (bry - tly) : 0.0f;
        float pred_iou = inter / (bw * bh + gwv * ghv - inter);
        float iou      = inter / (bw * bh + gwv * ghv - inter + 1e-16f);
        v_iou = 1.0f - iou * iou;

        float cl = 0.0f;
#pragma unroll 8
        for (int c = 0; c < CC; c++) {
            float xl = o[5 + c];
            float t  = (c == mc) ? pred_iou : 0.0f;
            cl += fmaxf(xl, 0.0f) - xl * t + log1pf(expf(-fabsf(xl)));
        }
        v_cls = cl;

        float st = stA[a];
        float t0 = gxv / st - xsA[a];
        float t1 = gyv / st - ysA[a];
        float t2 = logf(gwv / st + 1e-8f);
        float t3 = logf(ghv / st + 1e-8f);
        const float* op = orig + (size_t)(b * AA + a) * 4;
        v_l1 = fabsf(op[0] - t0) + fabsf(op[1] - t1) +
               fabsf(op[2] - t2) + fabsf(op[3] - t3);
    }
    float r;
    r = blockSum(v_iou, s); if (threadIdx.x == 0) atomicAdd(&d_acc[0], (double)r);
    r = blockSum(v_obj, s); if (threadIdx.x == 0) atomicAdd(&d_acc[1], (double)r);
    r = blockSum(v_cls, s); if (threadIdx.x == 0) atomicAdd(&d_acc[2], (double)r);
    r = blockSum(v_l1,  s); if (threadIdx.x == 0) atomicAdd(&d_acc[3], (double)r);
}

// ---------------- kernel 6: finalize + reset accumulators for next replay ----
__global__ void k_final(float* out) {
    int tid = threadIdx.x;
    if (tid == 0) {
        int tot = 0;
        for (int b2 = 0; b2 < BB; b2++) tot += d_mcnt[b2];
        double nfg = (double)tot;
        if (nfg < 1.0) nfg = 1.0;
        float liou = (float)(5.0 * d_acc[0] / nfg);
        float lobj = (float)(d_acc[1] / nfg);
        float lcls = (float)(d_acc[2] / nfg);
        float ll1  = (float)(d_acc[3] / nfg);
        out[0] = liou + lobj + lcls + ll1;
        out[1] = liou;
        out[2] = lobj;
        out[3] = lcls;
        out[4] = ll1;
        out[5] = (float)(nfg / (double)(BB * GG));
    }
    __syncthreads();
    d_mcnt[tid] = 0;
    if (tid < 6) d_acc[tid] = 0.0;
}

// ---------------- launch ----------------
extern "C" void kernel_launch(void* const* d_in, const int* in_sizes, int n_in,
                              void* d_out, int out_size) {
    const float* outputs = (const float*)d_in[0];
    const float* origin  = (const float*)d_in[1];
    const float* labels  = (const float*)d_in[2];
    const float* xs      = (const float*)d_in[3];
    const float* ys      = (const float*)d_in[4];
    const float* st      = (const float*)d_in[5];

    k_isin<<<dim3((AA + 255) / 256, BB), 256>>>(labels, outputs);
    k_scan<<<BB, 1024>>>();
    k_prep<<<dim3(SP / 8, BB), 128>>>(outputs);
    k_pairsel<<<BB * GG, 256>>>(outputs, labels);
    k_fgloss<<<dim3(MM / 128, BB), 128>>>(outputs, origin, labels, xs, ys, st);
    k_final<<<1, 32>>>((float*)d_out);
}

// round 12
// speedup vs baseline: 1.7238x; 1.0429x over previous
#include <cuda_runtime.h>
#include <math.h>
#include <float.h>

#define BB 32
#define AA 8400
#define GG 40
#define CC 80
#define ROW 85
#define SP 1536      // max candidates per batch; true bound ~1080
#define SPW (SP/32)  // 48 u32 words of transposed in-region bits per (b,g)
#define MM 512       // max matched anchors per batch
#define SL 64        // in-region pairs per (b,g) cap (geometric bound ~48)

// ---------------- scratch (device globals; zero-init at load) ----------------
__device__ unsigned long long d_match[BB * AA];
__device__ unsigned long long d_inin [BB * AA];
__device__ unsigned long long d_cinin[BB * SP];
__device__ unsigned d_ginin[BB * GG * SPW];   // transposed: bit c of word -> cand
__device__ int    d_fgidx[BB * SP];
__device__ int    d_inv  [BB * AA];
__device__ int    d_fgcnt[BB];
__device__ int    d_mcnt [BB];     // zeroed by k_final each run
__device__ int    d_midx [BB * MM];
__device__ double d_acc[6];        // zeroed by k_final each run
__device__ float4 d_cbox [BB * SP];   // x1,y1,x2,y2
__device__ float4 d_cmeta[BB * SP];   // area, obj, suml, -

// ---------------- block reduction helper ----------------
__device__ __forceinline__ float blockSum(float v, float* s) {
    int tid = threadIdx.x;
#pragma unroll
    for (int o = 16; o > 0; o >>= 1) v += __shfl_xor_sync(0xffffffffu, v, o);
    if ((tid & 31) == 0) s[tid >> 5] = v;
    __syncthreads();
    float r = 0.0f;
    if (tid < (blockDim.x >> 5)) r = s[tid];
#pragma unroll
    for (int o = 4; o > 0; o >>= 1) r += __shfl_xor_sync(0xffffffffu, r, o);
    __syncthreads();
    return r;   // valid in thread 0
}

// descending compare-and-swap
#define CASD(a, b) { float _h = fmaxf(a, b), _l = fminf(a, b); a = _h; b = _l; }

// ---------------- kernel 1: analytic mask + fg-independent obj BCE ----------
__global__ void k_isin(const float* __restrict__ labels,
                       const float* __restrict__ outp) {
    __shared__ float sgx[GG], sgy[GG];
    __shared__ float s[8];
    int b = blockIdx.y;
    int tid = threadIdx.x;
    if (tid < GG) {
        sgx[tid] = labels[(b * GG + tid) * 5 + 1];
        sgy[tid] = labels[(b * GG + tid) * 5 + 2];
    }
    // zero the transposed in-region bits (61440 words) across the grid
    int gt = (blockIdx.y * gridDim.x + blockIdx.x) * blockDim.x + tid;
    if (gt < BB * GG * SPW) d_ginin[gt] = 0u;
    __syncthreads();
    int a = blockIdx.x * blockDim.x + tid;
    float vo = 0.0f;
    if (a < AA) {
        float sc; int n, rel;
        if (a < 6400)      { sc = 8.0f;  n = 80; rel = a;        }
        else if (a < 8000) { sc = 16.0f; n = 40; rel = a - 6400; }
        else               { sc = 32.0f; n = 20; rel = a - 8000; }
        float xc = ((float)(rel % n) + 0.5f) * sc;
        float yc = ((float)(rel / n) + 0.5f) * sc;
        float r  = 1.5f * sc;
        unsigned long long m = 0ull;
#pragma unroll 8
        for (int g = 0; g < GG; g++) {
            bool in = (xc > sgx[g] - r) && (xc < sgx[g] + r) &&
                      (yc > sgy[g] - r) && (yc < sgy[g] + r);
            if (in) m |= (1ull << g);
        }
        d_inin [b * AA + a] = m;
        d_match[b * AA + a] = 0ull;
        float x = outp[(size_t)(b * AA + a) * ROW + 4];
        vo = fmaxf(x, 0.0f) + __logf(1.0f + __expf(-fabsf(x)));
    }
    float r = blockSum(vo, s);
    if (tid == 0) atomicAdd(&d_acc[1], (double)r);
}

// ---------------- kernel 2: ordered compaction + transposed mask write -------
__global__ void __launch_bounds__(1024) k_scan() {
    __shared__ int wcnt[32];
    int b = blockIdx.x;
    int tid = threadIdx.x, wid = tid >> 5, lane = tid & 31;
    const int CH = 263;
    int base = wid * CH;
    int cnt = 0;
#pragma unroll
    for (int k = 0; k < 9; k++) {
        int loc = k * 32 + lane;
        int a = base + loc;
        bool p = (loc < CH) && (a < AA) && (d_inin[b * AA + a] != 0ull);
        cnt += __popc(__ballot_sync(0xffffffffu, p));
    }
    if (lane == 0) wcnt[wid] = cnt;
    __syncthreads();
    if (wid == 0) {
        int v = wcnt[lane];
#pragma unroll
        for (int o = 1; o < 32; o <<= 1) {
            int u = __shfl_up_sync(0xffffffffu, v, o);
            if (lane >= o) v += u;
        }
        wcnt[lane] = v;
    }
    __syncthreads();
    if (tid == 0) {
        int tot = wcnt[31];
        d_fgcnt[b] = tot < SP ? tot : SP;
    }
    int pos = wcnt[wid] - cnt;
#pragma unroll
    for (int k = 0; k < 9; k++) {
        int loc = k * 32 + lane;
        int a = base + loc;
        unsigned long long m =
            ((loc < CH) && (a < AA)) ? d_inin[b * AA + a] : 0ull;
        unsigned bal = __ballot_sync(0xffffffffu, m != 0ull);
        int my = __popc(bal & ((1u << lane) - 1u));
        if (m != 0ull && pos + my < SP) {
            int cp = pos + my;
            d_fgidx[b * SP + cp] = a;
            d_inv  [b * AA + a]  = cp;
            // transposed bits: for each in-region g, set bit cp
            unsigned long long mm = m;
            while (mm) {
                int g = __ffsll((long long)mm) - 1;
                mm &= mm - 1;
                atomicOr(&d_ginin[(b * GG + g) * SPW + (cp >> 5)],
                         1u << (cp & 31));
            }
        }
        pos += __popc(bal);
    }
}

// ---------------- kernel 3: candidate prep + suml (16 lanes / candidate) -----
__global__ void __launch_bounds__(128) k_prep(const float* __restrict__ outp) {
    int b   = blockIdx.y;
    int cnt = d_fgcnt[b];
    if (blockIdx.x * 8 >= cnt) return;
    int tid  = threadIdx.x;
    int lane = tid & 31, warp = tid >> 5;
    int grp  = lane >> 4, sub = lane & 15;
    int i    = blockIdx.x * 8 + warp * 2 + grp;
    bool valid = (i < cnt);
    int ic = valid ? i : (cnt - 1);
    int a  = d_fgidx[b * SP + ic];
    const float* o = outp + (size_t)(b * AA + a) * ROW;
    float obj = o[4];
    float prod = 1.0f;
#pragma unroll
    for (int c = 0; c < 5; c++) {
        float x = o[5 + sub * 5 + c] * obj;
        prod *= (1.0f - x * rsqrtf(x));
    }
    float l = __logf(prod);
    l += __shfl_xor_sync(0xffffffffu, l, 1);
    l += __shfl_xor_sync(0xffffffffu, l, 2);
    l += __shfl_xor_sync(0xffffffffu, l, 4);
    l += __shfl_xor_sync(0xffffffffu, l, 8);
    if (sub == 0 && valid) {
        float bx = o[0], by = o[1], bw = o[2], bh = o[3];
        int idx = b * SP + i;
        d_cbox [idx] = make_float4(bx - bw * 0.5f, by - bh * 0.5f,
                                   bx + bw * 0.5f, by + bh * 0.5f);
        d_cmeta[idx] = make_float4(bw * bh, obj, l, 0.0f);
        d_cinin[idx] = d_inin[b * AA + a];
    }
}

// ---------------- kernel 4: fused pair iou + dynamic_k + top-k select -------
// Block per (b,g), 256 threads x 6 candidates.
// j-loop: 1 float4 load + uniform mask word; iou in FMA pipe.
// Phase A: lane sort-6 + pop-head warp top-10 with zero early-exit.
// Phase B: k min-passes collecting winners, then parallel atomicOr.
__global__ void __launch_bounds__(256) k_pairsel(const float* __restrict__ outp,
                                                 const float* __restrict__ labels) {
    __shared__ unsigned swtop[8 * 10];
    __shared__ unsigned long long swin[10];
    __shared__ unsigned long long slist[SL];
    __shared__ int scnt;
    int bg = blockIdx.x;
    int b  = bg / GG;
    int g  = bg - b * GG;
    int tid = threadIdx.x, lane = tid & 31, wid = tid >> 5;
    int N = d_fgcnt[b];
    if (tid == 0) scnt = 0;
    if (tid < 80) swtop[tid] = 0u;

    const float* L = labels + (b * GG + g) * 5;   // uniform broadcast loads
    int   gc  = (int)L[0];
    float gxv = L[1], gyv = L[2], gwv = L[3], ghv = L[4];
    float qx1 = gxv - gwv * 0.5f, qx2 = gxv + gwv * 0.5f;
    float qy1 = gyv - ghv * 0.5f, qy2 = gyv + ghv * 0.5f;
    float qar = gwv * ghv;
    const unsigned* gin = d_ginin + (size_t)bg * SPW;
    __syncthreads();                              // scnt/swtop visible

    float s0, s1, s2, s3, s4, s5;
    float* sv[6] = {&s0, &s1, &s2, &s3, &s4, &s5};
#pragma unroll
    for (int j = 0; j < 6; j++) {
        int i = tid + j * 256;
        float iou = 0.0f;
        bool inreg = false;
        if (i < N) {
            float4 box = d_cbox[b * SP + i];
            float area = (box.z - box.x) * (box.w - box.y);
            float w = fminf(box.z, qx2) - fmaxf(box.x, qx1);
            float h = fminf(box.w, qy2) - fmaxf(box.y, qy1);
            float inter = fmaxf(w, 0.0f) * fmaxf(h, 0.0f);
            float den = area + qar - inter;
            float y = __uint_as_float(0x7EF311C3u - __float_as_uint(den));
            y = y * (2.0f - den * y);
            y = y * (2.0f - den * y);
            iou = inter * y;
            unsigned wrd = gin[wid + 8 * j];      // warp-uniform word
            inreg = (wrd >> lane) & 1u;
        }
        *sv[j] = iou;
        unsigned mb = __ballot_sync(0xffffffffu, inreg);
        if (mb) {
            int leader = __ffs(mb) - 1;
            int base = 0;
            if (lane == leader) base = atomicAdd(&scnt, __popc(mb));
            base = __shfl_sync(0xffffffffu, base, leader);
            if (inreg) {
                int p = base + __popc(mb & ((1u << lane) - 1u));
                if (p < SL)
                    slist[p] = ((unsigned long long)__float_as_uint(iou) << 32)
                               | (unsigned)i;
            }
        }
    }

    // phase A: sort 6 desc (12-CAS network), then pop-head top-10
    CASD(s0, s5) CASD(s1, s3) CASD(s2, s4)
    CASD(s1, s2) CASD(s3, s4)
    CASD(s0, s3) CASD(s2, s5)
    CASD(s0, s1) CASD(s2, s3) CASD(s4, s5)
    CASD(s1, s2) CASD(s3, s4)
    for (int t = 0; t < 10; t++) {
        float wmax = s0;
#pragma unroll
        for (int o = 16; o > 0; o >>= 1)
            wmax = fmaxf(wmax, __shfl_xor_sync(0xffffffffu, wmax, o));
        if (wmax <= 0.0f) break;                  // rest are zeros (pre-zeroed)
        unsigned ball = __ballot_sync(0xffffffffu, s0 == wmax);
        if (lane == (__ffs(ball) - 1)) {          // owner pops its head
            s0 = s1; s1 = s2; s2 = s3; s3 = s4; s4 = s5; s5 = 0.0f;
        }
        if (lane == 0) swtop[wid * 10 + t] = __float_as_uint(wmax);
    }
    __syncthreads();                              // appends + swtop done

    // cost burst: parallel over the <=SL in-region entries
    int M = scnt; if (M > SL) M = SL;
    if (tid < M) {
        unsigned long long e = slist[tid];
        int i = (int)(unsigned)(e & 0xFFFFFFFFull);
        float iou = __uint_as_float((unsigned)(e >> 32));
        int idx = b * SP + i;
        float4 meta = d_cmeta[idx];
        int a = d_fgidx[idx];
        float xg = outp[(size_t)(b * AA + a) * ROW + 5 + gc] * meta.y;
        float pg = xg * rsqrtf(xg);
        float cost = -meta.z - (0.5f * __logf(xg) - __logf(1.0f - pg))
                     - 3.0f * __logf(iou + 1e-8f);
        unsigned cb = __float_as_uint(cost);
        cb = (cb & 0x80000000u) ? ~cb : (cb | 0x80000000u);
        slist[tid] = ((unsigned long long)cb << 32) | (unsigned)i;
    }
    __syncthreads();

    if (wid != 0) return;
    // warp0: merge 80 per-warp tops, sum top-10 descending
    float m0 = __uint_as_float(swtop[lane]);
    float m1 = __uint_as_float(swtop[lane + 32]);
    float m2 = (lane + 64 < 80) ? __uint_as_float(swtop[lane + 64]) : 0.0f;
    CASD(m0, m1) CASD(m0, m2) CASD(m1, m2)        // sort 3 desc
    float sum = 0.0f;
    for (int t = 0; t < 10; t++) {
        float wmax = m0;
#pragma unroll
        for (int o = 16; o > 0; o >>= 1)
            wmax = fmaxf(wmax, __shfl_xor_sync(0xffffffffu, wmax, o));
        if (wmax <= 0.0f) break;
        unsigned ball = __ballot_sync(0xffffffffu, m0 == wmax);
        if (lane == (__ffs(ball) - 1)) { m0 = m1; m1 = m2; m2 = 0.0f; }
        sum += wmax;
    }
    int k = (int)sum;
    if (k < 1)  k = 1;
    if (k > 10) k = 10;

    // phase B: k smallest (cost, idx) keys; collect winners, batch atomics
    unsigned long long kk0 = (lane      < M) ? slist[lane]      : ~0ull;
    unsigned long long kk1 = (lane + 32 < M) ? slist[lane + 32] : ~0ull;
    int nwin = 0;
    for (int t = 0; t < k; t++) {
        unsigned long long lbest = (kk0 < kk1) ? kk0 : kk1;
        unsigned long long wmin = lbest;
#pragma unroll
        for (int o = 16; o > 0; o >>= 1) {
            unsigned long long oth = __shfl_xor_sync(0xffffffffu, wmin, o);
            if (oth < wmin) wmin = oth;
        }
        if (wmin == ~0ull) break;
        unsigned ball = __ballot_sync(0xffffffffu, lbest == wmin);
        if (lane == (__ffs(ball) - 1)) {          // keys unique: remove
            if (kk0 == wmin) kk0 = ~0ull; else kk1 = ~0ull;
        }
        if (lane == 0) swin[t] = wmin;
        nwin++;
    }
    __syncwarp();
    if (lane < nwin) {                            // parallel atomics (distinct a)
        int i = (int)(unsigned)(swin[lane] & 0xFFFFFFFFull);
        int a = d_fgidx[b * SP + i];
        unsigned long long old = atomicOr(&d_match[b * AA + a], 1ull << g);
        if (old == 0ull) {                        // first match -> compact
            int pos = atomicAdd(&d_mcnt[b], 1);
            if (pos < MM) d_midx[b * MM + pos] = a;
        }
    }
}

// ---------------- kernel 5: heavy losses on matched anchors only -------------
__global__ void __launch_bounds__(128) k_fgloss(const float* __restrict__ outp,
                                                const float* __restrict__ orig,
                                                const float* __restrict__ labels,
                                                const float* __restrict__ xsA,
                                                const float* __restrict__ ysA,
                                                const float* __restrict__ stA) {
    __shared__ float s[8];
    int b = blockIdx.y;
    int j = blockIdx.x * 128 + threadIdx.x;
    float v_iou = 0.0f, v_cls = 0.0f, v_l1 = 0.0f, v_obj = 0.0f;
    int mc2 = d_mcnt[b]; if (mc2 > MM) mc2 = MM;
    if (j < mc2) {
        int a = d_midx[b * MM + j];
        unsigned long long m = d_match[b * AA + a];
        int i = d_inv[b * AA + a];
        int idx = b * SP + i;
        int mg;
        if (__popcll(m) > 1) {
            // best_gt = argmin cost over in-region g's (identical formulas to
            // k_pairsel; out-of-region +1e6 costs can never win)
            float4 box  = d_cbox [idx];
            float4 meta = d_cmeta[idx];
            unsigned long long mm = d_cinin[idx];
            const float* orow = outp + (size_t)(b * AA + a) * ROW;
            float best = FLT_MAX; mg = 0;
            while (mm) {
                int g = __ffsll((long long)mm) - 1;
                mm &= mm - 1;
                const float* L = labels + (b * GG + g) * 5;
                int   gc  = (int)L[0];
                float gxv = L[1], gyv = L[2], gwv = L[3], ghv = L[4];
                float qx1 = gxv - gwv * 0.5f, qx2 = gxv + gwv * 0.5f;
                float qy1 = gyv - ghv * 0.5f, qy2 = gyv + ghv * 0.5f;
                float qar = gwv * ghv;
                float w = fminf(box.z, qx2) - fmaxf(box.x, qx1);
                float h = fminf(box.w, qy2) - fmaxf(box.y, qy1);
                float inter = fmaxf(w, 0.0f) * fmaxf(h, 0.0f);
                float den = meta.x + qar - inter;
                float y = __uint_as_float(0x7EF311C3u - __float_as_uint(den));
                y = y * (2.0f - den * y);
                y = y * (2.0f - den * y);
                float iou = inter * y;
                float xg = orow[5 + gc] * meta.y;
                float pg = xg * rsqrtf(xg);
                float c = -meta.z - (0.5f * __logf(xg) - __logf(1.0f - pg))
                          - 3.0f * __logf(iou + 1e-8f);
                if (c < best) { best = c; mg = g; }
            }
        } else {
            mg = __ffsll((long long)m) - 1;
        }
        const float* L = labels + (b * GG + mg) * 5;
        int   mc = (int)L[0];
        float gxv = L[1], gyv = L[2], gwv = L[3], ghv = L[4];

        const float* o = outp + (size_t)(b * AA + a) * ROW;
        v_obj = -o[4];                       // fg-dependent obj BCE term
        float bx = o[0], by = o[1], bw = o[2], bh = o[3];
        float tlx = fmaxf(bx - bw * 0.5f, gxv - gwv * 0.5f);
        float tly = fmaxf(by - bh * 0.5f, gyv - ghv * 0.5f);
        float brx = fminf(bx + bw * 0.5f, gxv + gwv * 0.5f);
        float bry = fminf(by + bh * 0.5f, gyv + ghv * 0.5f);
        float inter = (tlx < brx && tly < bry) ? (brx - tlx) * (bry - tly) : 0.0f;
        float pred_iou = inter / (bw * bh + gwv * ghv - inter);
        float iou      = inter / (bw * bh + gwv * ghv - inter + 1e-16f);
        v_iou = 1.0f - iou * iou;

        float cl = 0.0f;
#pragma unroll 8
        for (int c = 0; c < CC; c++) {
            float xl = o[5 + c];
            float t  = (c == mc) ? pred_iou : 0.0f;
            cl += fmaxf(xl, 0.0f) - xl * t + log1pf(expf(-fabsf(xl)));
        }
        v_cls = cl;

        float st = stA[a];
        float t0 = gxv / st - xsA[a];
        float t1 = gyv / st - ysA[a];
        float t2 = logf(gwv / st + 1e-8f);
        float t3 = logf(ghv / st + 1e-8f);
        const float* op = orig + (size_t)(b * AA + a) * 4;
        v_l1 = fabsf(op[0] - t0) + fabsf(op[1] - t1) +
               fabsf(op[2] - t2) + fabsf(op[3] - t3);
    }
    float r;
    r = blockSum(v_iou, s); if (threadIdx.x == 0) atomicAdd(&d_acc[0], (double)r);
    r = blockSum(v_obj, s); if (threadIdx.x == 0) atomicAdd(&d_acc[1], (double)r);
    r = blockSum(v_cls, s); if (threadIdx.x == 0) atomicAdd(&d_acc[2], (double)r);
    r = blockSum(v_l1,  s); if (threadIdx.x == 0) atomicAdd(&d_acc[3], (double)r);
}

// ---------------- kernel 6: finalize + reset accumulators for next replay ----
__global__ void k_final(float* out) {
    int tid = threadIdx.x;
    if (tid == 0) {
        int tot = 0;
        for (int b2 = 0; b2 < BB; b2++) tot += d_mcnt[b2];
        double nfg = (double)tot;
        if (nfg < 1.0) nfg = 1.0;
        float liou = (float)(5.0 * d_acc[0] / nfg);
        float lobj = (float)(d_acc[1] / nfg);
        float lcls = (float)(d_acc[2] / nfg);
        float ll1  = (float)(d_acc[3] / nfg);
        out[0] = liou + lobj + lcls + ll1;
        out[1] = liou;
        out[2] = lobj;
        out[3] = lcls;
        out[4] = ll1;
        out[5] = (float)(nfg / (double)(BB * GG));
    }
    __syncthreads();
    d_mcnt[tid] = 0;
    if (tid < 6) d_acc[tid] = 0.0;
}

// ---------------- launch ----------------
extern "C" void kernel_launch(void* const* d_in, const int* in_sizes, int n_in,
                              void* d_out, int out_size) {
    const float* outputs = (const float*)d_in[0];
    const float* origin  = (const float*)d_in[1];
    const float* labels  = (const float*)d_in[2];
    const float* xs      = (const float*)d_in[3];
    const float* ys      = (const float*)d_in[4];
    const float* st      = (const float*)d_in[5];

    k_isin<<<dim3((AA + 255) / 256, BB), 256>>>(labels, outputs);
    k_scan<<<BB, 1024>>>();
    k_prep<<<dim3(SP / 8, BB), 128>>>(outputs);
    k_pairsel<<<BB * GG, 256>>>(outputs, labels);
    k_fgloss<<<dim3(MM / 128, BB), 128>>>(outputs, origin, labels, xs, ys, st);
    k_final<<<1, 32>>>((float*)d_out);
}